// round 2
// baseline (speedup 1.0000x reference)
#include <cuda_runtime.h>

#define Bz 2
#define Tt 2048
#define Dd 2048
#define Hh 16
#define HD 128
#define Mrows (Bz*Tt)

// Scratch (static device globals: allocation-free, graph-capture safe)
__device__ float g_q[Bz*Hh*Tt*HD];   // [B,H,T,HD]
__device__ float g_k[Bz*Hh*Tt*HD];
__device__ float g_v[Bz*Hh*Tt*HD];
__device__ float g_a[Bz*Tt*Dd];      // attention output, [B,T,D]

// ---------------------------------------------------------------------------
// SGEMM (NT): C[m,n] = sum_k A[m,k] * B[n,k]  (+bias).  A:[M,K], B:[N,K] row-major.
// qkv_mode=1 scatters C into [B,H,T,HD] layout (tile n-block == one head).
// ---------------------------------------------------------------------------
#define GBM 128
#define GBN 128
#define GBK 16

__global__ __launch_bounds__(256) void sgemm_nt(
    const float* __restrict__ A, const float* __restrict__ B,
    const float* __restrict__ bias, float* __restrict__ C,
    int M, int N, int K, int qkv_mode)
{
    __shared__ float As[GBK][GBM];
    __shared__ float Bs[GBK][GBN];
    const int tid = threadIdx.x;
    const int tx = tid & 15, ty = tid >> 4;
    const int row0 = blockIdx.y * GBM;
    const int col0 = blockIdx.x * GBN;
    const int lr = tid >> 2;          // 0..63
    const int lk = (tid & 3) * 4;     // 0,4,8,12

    float acc[8][8];
    #pragma unroll
    for (int i = 0; i < 8; i++)
        #pragma unroll
        for (int j = 0; j < 8; j++) acc[i][j] = 0.f;

    for (int kt = 0; kt < K; kt += GBK) {
        #pragma unroll
        for (int h = 0; h < 2; h++) {
            int r = lr + h * 64;
            float4 av = *(const float4*)(A + (size_t)(row0 + r) * K + kt + lk);
            As[lk + 0][r] = av.x; As[lk + 1][r] = av.y;
            As[lk + 2][r] = av.z; As[lk + 3][r] = av.w;
            float4 bv = *(const float4*)(B + (size_t)(col0 + r) * K + kt + lk);
            Bs[lk + 0][r] = bv.x; Bs[lk + 1][r] = bv.y;
            Bs[lk + 2][r] = bv.z; Bs[lk + 3][r] = bv.w;
        }
        __syncthreads();
        #pragma unroll
        for (int kk = 0; kk < GBK; kk++) {
            float a[8], b[8];
            *(float4*)&a[0] = *(const float4*)&As[kk][ty * 8];
            *(float4*)&a[4] = *(const float4*)&As[kk][ty * 8 + 4];
            *(float4*)&b[0] = *(const float4*)&Bs[kk][tx * 4];
            *(float4*)&b[4] = *(const float4*)&Bs[kk][64 + tx * 4];
            #pragma unroll
            for (int i = 0; i < 8; i++)
                #pragma unroll
                for (int j = 0; j < 8; j++)
                    acc[i][j] = fmaf(a[i], b[j], acc[i][j]);
        }
        __syncthreads();
    }

    const int na = col0 + tx * 4;
    const int nb = na + 64;
    #pragma unroll
    for (int i = 0; i < 8; i++) {
        int m = row0 + ty * 8 + i;
        float4 v0 = make_float4(acc[i][0], acc[i][1], acc[i][2], acc[i][3]);
        float4 v1 = make_float4(acc[i][4], acc[i][5], acc[i][6], acc[i][7]);
        if (qkv_mode) {
            int bb = m >> 11;             // m / T
            int t  = m & (Tt - 1);
            int h  = na >> 7;             // head (tile-aligned to 128)
            size_t base = ((size_t)(bb * Hh + h) * Tt + t) * HD;
            *(float4*)(C + base + (na & 127)) = v0;
            *(float4*)(C + base + (nb & 127)) = v1;
        } else {
            if (bias) {
                v0.x += bias[na];     v0.y += bias[na + 1];
                v0.z += bias[na + 2]; v0.w += bias[na + 3];
                v1.x += bias[nb];     v1.y += bias[nb + 1];
                v1.z += bias[nb + 2]; v1.w += bias[nb + 3];
            }
            *(float4*)(C + (size_t)m * N + na) = v0;
            *(float4*)(C + (size_t)m * N + nb) = v1;
        }
    }
}

// ---------------------------------------------------------------------------
// Flash-style causal attention, fp32. 64x64 tiles, HD=128.
// Q/K/V in [B*H][T][HD]; output written to [B,T,D].
// ---------------------------------------------------------------------------
#define ABM 64
#define ABN 64
// smem: Qs[128][64] + Ks[128][64] + Vs[64][132] + Ps[64][68]
#define ATTN_SMEM ((128*64 + 128*64 + 64*132 + 64*68) * 4)

__global__ __launch_bounds__(256) void attn_kernel(
    const float* __restrict__ Q, const float* __restrict__ K,
    const float* __restrict__ V, float* __restrict__ Out)
{
    extern __shared__ float sm[];
    float* Qs = sm;                 // [128][64]  (transposed: [hd][m])
    float* Ks = Qs + 128 * 64;      // [128][64]  ([hd][n])
    float* Vs = Ks + 128 * 64;      // [64][132]  ([n][hd], padded)
    float* Ps = Vs + 64 * 132;      // [64][68]   ([n][m], padded)

    const int tid = threadIdx.x;
    const int tx = tid & 15, ty = tid >> 4;
    const int qblk = (int)gridDim.x - 1 - (int)blockIdx.x;  // longest first
    const int bh = blockIdx.y;
    const float* Qp = Q + ((size_t)bh * Tt + qblk * ABM) * HD;
    const float* Kp = K + (size_t)bh * Tt * HD;
    const float* Vp = V + (size_t)bh * Tt * HD;

    // Load Q tile (64x128) transposed into Qs[hd][m]
    #pragma unroll
    for (int i = 0; i < 8; i++) {
        int f = tid * 8 + i;
        int r = f >> 5;       // row (m) 0..63
        int c4 = f & 31;      // float4 col in hd
        float4 qv = *(const float4*)(Qp + (size_t)r * HD + c4 * 4);
        Qs[(c4 * 4 + 0) * 64 + r] = qv.x;
        Qs[(c4 * 4 + 1) * 64 + r] = qv.y;
        Qs[(c4 * 4 + 2) * 64 + r] = qv.z;
        Qs[(c4 * 4 + 3) * 64 + r] = qv.w;
    }

    float mi[4], li[4], o[4][8];
    #pragma unroll
    for (int r = 0; r < 4; r++) {
        mi[r] = -1e30f; li[r] = 0.f;
        #pragma unroll
        for (int c = 0; c < 8; c++) o[r][c] = 0.f;
    }

    const float scale = 0.08838834764831845f;  // 1/sqrt(128)
    const int qi0 = qblk * ABM + ty * 4;

    for (int jt = 0; jt <= qblk; jt++) {
        __syncthreads();   // previous PV done before overwriting K/V/P
        // Load K tile transposed + V tile direct
        #pragma unroll
        for (int i = 0; i < 8; i++) {
            int f = tid * 8 + i;
            int r = f >> 5;
            int c4 = f & 31;
            float4 kv = *(const float4*)(Kp + (size_t)(jt * ABN + r) * HD + c4 * 4);
            Ks[(c4 * 4 + 0) * 64 + r] = kv.x;
            Ks[(c4 * 4 + 1) * 64 + r] = kv.y;
            Ks[(c4 * 4 + 2) * 64 + r] = kv.z;
            Ks[(c4 * 4 + 3) * 64 + r] = kv.w;
            float4 vv = *(const float4*)(Vp + (size_t)(jt * ABN + r) * HD + c4 * 4);
            *(float4*)&Vs[r * 132 + c4 * 4] = vv;
        }
        __syncthreads();

        // S = Q K^T  (each thread: 4 rows x 4 cols)
        float s[4][4];
        #pragma unroll
        for (int r = 0; r < 4; r++)
            #pragma unroll
            for (int c = 0; c < 4; c++) s[r][c] = 0.f;

        #pragma unroll 4
        for (int kk = 0; kk < HD; kk++) {
            float4 qa = *(const float4*)&Qs[kk * 64 + ty * 4];
            float4 kb = *(const float4*)&Ks[kk * 64 + tx * 4];
            float aq[4] = {qa.x, qa.y, qa.z, qa.w};
            float bk[4] = {kb.x, kb.y, kb.z, kb.w};
            #pragma unroll
            for (int r = 0; r < 4; r++)
                #pragma unroll
                for (int c = 0; c < 4; c++)
                    s[r][c] = fmaf(aq[r], bk[c], s[r][c]);
        }

        const int kj0 = jt * ABN + tx * 4;
        const bool diag = (jt == qblk);
        #pragma unroll
        for (int r = 0; r < 4; r++)
            #pragma unroll
            for (int c = 0; c < 4; c++) {
                float val = s[r][c] * scale;
                if (diag && (kj0 + c > qi0 + r)) val = -1e30f;
                s[r][c] = val;
            }

        // Online softmax per row (reduce over 16 tx-lanes within half-warp)
        #pragma unroll
        for (int r = 0; r < 4; r++) {
            float mt = fmaxf(fmaxf(s[r][0], s[r][1]), fmaxf(s[r][2], s[r][3]));
            #pragma unroll
            for (int off = 8; off; off >>= 1)
                mt = fmaxf(mt, __shfl_xor_sync(0xffffffffu, mt, off));
            float mnew = fmaxf(mi[r], mt);
            float alpha = __expf(mi[r] - mnew);
            float lt = 0.f;
            #pragma unroll
            for (int c = 0; c < 4; c++) {
                float p = __expf(s[r][c] - mnew);
                s[r][c] = p;
                lt += p;
            }
            #pragma unroll
            for (int off = 8; off; off >>= 1)
                lt += __shfl_xor_sync(0xffffffffu, lt, off);
            li[r] = li[r] * alpha + lt;
            mi[r] = mnew;
            #pragma unroll
            for (int c = 0; c < 8; c++) o[r][c] *= alpha;
        }

        // Stage P transposed: Ps[n][m]
        #pragma unroll
        for (int c = 0; c < 4; c++)
            *(float4*)&Ps[(tx * 4 + c) * 68 + ty * 4] =
                make_float4(s[0][c], s[1][c], s[2][c], s[3][c]);
        __syncthreads();

        // O += P V  (each thread: 4 rows x 8 cols, cols split {tx*4, 64+tx*4})
        #pragma unroll 2
        for (int j = 0; j < ABN; j++) {
            float4 p4 = *(const float4*)&Ps[j * 68 + ty * 4];
            float4 va = *(const float4*)&Vs[j * 132 + tx * 4];
            float4 vb = *(const float4*)&Vs[j * 132 + 64 + tx * 4];
            float pr[4] = {p4.x, p4.y, p4.z, p4.w};
            float vv[8] = {va.x, va.y, va.z, va.w, vb.x, vb.y, vb.z, vb.w};
            #pragma unroll
            for (int r = 0; r < 4; r++)
                #pragma unroll
                for (int c = 0; c < 8; c++)
                    o[r][c] = fmaf(pr[r], vv[c], o[r][c]);
        }
    }

    // Epilogue: normalize and write to [B,T,D]
    const int b = bh >> 4, h = bh & 15;
    float* Ob = Out + ((size_t)(b * Tt + qblk * ABM + ty * 4)) * Dd + h * HD;
    #pragma unroll
    for (int r = 0; r < 4; r++) {
        float inv = 1.0f / li[r];
        float4 w0 = make_float4(o[r][0] * inv, o[r][1] * inv, o[r][2] * inv, o[r][3] * inv);
        float4 w1 = make_float4(o[r][4] * inv, o[r][5] * inv, o[r][6] * inv, o[r][7] * inv);
        *(float4*)(Ob + (size_t)r * Dd + tx * 4) = w0;
        *(float4*)(Ob + (size_t)r * Dd + 64 + tx * 4) = w1;
    }
}

// ---------------------------------------------------------------------------
extern "C" void kernel_launch(void* const* d_in, const int* in_sizes, int n_in,
                              void* d_out, int out_size)
{
    const float* x  = (const float*)d_in[0];
    const float* Wq = (const float*)d_in[1];
    const float* Wk = (const float*)d_in[2];
    const float* Wv = (const float*)d_in[3];
    const float* Wo = (const float*)d_in[4];
    const float* bo = (const float*)d_in[5];

    float *q, *k, *v, *a;
    cudaGetSymbolAddress((void**)&q, g_q);
    cudaGetSymbolAddress((void**)&k, g_k);
    cudaGetSymbolAddress((void**)&v, g_v);
    cudaGetSymbolAddress((void**)&a, g_a);

    dim3 gg(Dd / GBN, Mrows / GBM);   // (16, 32)

    // QKV projections, scattered to [B,H,T,HD]
    sgemm_nt<<<gg, 256>>>(x, Wq, nullptr, q, Mrows, Dd, Dd, 1);
    sgemm_nt<<<gg, 256>>>(x, Wk, nullptr, k, Mrows, Dd, Dd, 1);
    sgemm_nt<<<gg, 256>>>(x, Wv, nullptr, v, Mrows, Dd, Dd, 1);

    // Causal attention -> [B,T,D]
    cudaFuncSetAttribute(attn_kernel, cudaFuncAttributeMaxDynamicSharedMemorySize, ATTN_SMEM);
    attn_kernel<<<dim3(Tt / ABM, Bz * Hh), 256, ATTN_SMEM>>>(q, k, v, a);

    // Output projection + bias
    sgemm_nt<<<gg, 256>>>(a, Wo, bo, (float*)d_out, Mrows, Dd, Dd, 0);
}

// round 5
// speedup vs baseline: 1.6681x; 1.6681x over previous
#include <cuda_runtime.h>
#include <cstdint>

#define Bz 2
#define Tt 2048
#define Dd 2048
#define Hh 16
#define HD 128
#define Mrows (Bz*Tt)

// Scratch (static device globals: allocation-free, graph-capture safe)
__device__ float g_q[Bz*Hh*Tt*HD];   // [B,H,T,HD]
__device__ float g_k[Bz*Hh*Tt*HD];
__device__ float g_v[Bz*Hh*Tt*HD];
__device__ float g_a[Bz*Tt*Dd];      // attention output, [B,T,D]

// ===========================================================================
// mma.sync tf32 GEMM (NT): C[m,n] = sum_k A[m,k]*B[n,k] (+bias)
// CTA tile 128x128, BK=32. 8 warps (2x4), warp tile 64x32.
// m16n8k8 tf32 fragments, smem rows padded to 36 words (conflict-free).
// qkv_mode=1 scatters C into [B,H,T,HD] (n-tile == one head).
// ===========================================================================
#define TBM 128
#define TBN 128
#define TBK 32
#define NKT (Dd / TBK)            // 64
#define SSTRIDE 36                // 32 + 4 pad words
#define TILE_W (128 * SSTRIDE)    // words per operand buffer
#define TC_SMEM (4 * TILE_W * 4)  // 2 buffers x (A+B) = 73728 B

__device__ __forceinline__ uint32_t f2tf32(float x) {
    uint32_t r; asm("cvt.rna.tf32.f32 %0, %1;" : "=r"(r) : "f"(x)); return r;
}
__device__ __forceinline__ void mma1688(float* d, const uint32_t* a,
                                        const uint32_t* b, const float* c) {
    asm volatile(
        "mma.sync.aligned.m16n8k8.row.col.f32.tf32.tf32.f32 "
        "{%0,%1,%2,%3}, {%4,%5,%6,%7}, {%8,%9}, {%10,%11,%12,%13};"
        : "=f"(d[0]), "=f"(d[1]), "=f"(d[2]), "=f"(d[3])
        : "r"(a[0]), "r"(a[1]), "r"(a[2]), "r"(a[3]),
          "r"(b[0]), "r"(b[1]),
          "f"(c[0]), "f"(c[1]), "f"(c[2]), "f"(c[3]));
}

__global__ __launch_bounds__(256) void tc_gemm(
    const float* __restrict__ A, const float* __restrict__ B,
    const float* __restrict__ bias, float* __restrict__ C, int qkv_mode)
{
    extern __shared__ uint32_t smw[];
    uint32_t* sAb[2] = {smw,            smw + 2 * TILE_W};
    uint32_t* sBb[2] = {smw + TILE_W,   smw + 3 * TILE_W};

    const int tid = threadIdx.x;
    const int wid = tid >> 5;
    const int lane = tid & 31;
    const int grp = lane >> 2;      // 0..7
    const int tig = lane & 3;       // 0..3
    const int wm = (wid >> 2) * 64; // warp M offset: 0 / 64
    const int wn = (wid & 2 ? (wid & 3) : (wid & 3)) * 32; // 0/32/64/96
    const int row0 = blockIdx.y * TBM;
    const int col0 = blockIdx.x * TBN;

    // per-thread gmem load coords: 4 float4 chunks per operand per tile
    int lr[4], lc[4];
    #pragma unroll
    for (int i = 0; i < 4; i++) {
        int idx = tid + i * 256;
        lr[i] = idx >> 3;          // row 0..127
        lc[i] = (idx & 7) * 4;     // col 0,4,...,28
    }

    float acc[4][4][4];
    #pragma unroll
    for (int mt = 0; mt < 4; mt++)
        #pragma unroll
        for (int nt = 0; nt < 4; nt++)
            #pragma unroll
            for (int e = 0; e < 4; e++) acc[mt][nt][e] = 0.f;

    // ---- load tile 0 into buffer 0
    #pragma unroll
    for (int i = 0; i < 4; i++) {
        float4 av = *(const float4*)(A + (size_t)(row0 + lr[i]) * Dd + lc[i]);
        float4 bv = *(const float4*)(B + (size_t)(col0 + lr[i]) * Dd + lc[i]);
        uint32_t* pa = sAb[0] + lr[i] * SSTRIDE + lc[i];
        pa[0] = f2tf32(av.x); pa[1] = f2tf32(av.y); pa[2] = f2tf32(av.z); pa[3] = f2tf32(av.w);
        uint32_t* pb = sBb[0] + lr[i] * SSTRIDE + lc[i];
        pb[0] = f2tf32(bv.x); pb[1] = f2tf32(bv.y); pb[2] = f2tf32(bv.z); pb[3] = f2tf32(bv.w);
    }
    __syncthreads();

    for (int kt = 0; kt < NKT; kt++) {
        const int b = kt & 1;
        float4 pa[4], pb[4];
        const bool more = (kt + 1 < NKT);
        if (more) {
            const int k0 = (kt + 1) * TBK;
            #pragma unroll
            for (int i = 0; i < 4; i++) {
                pa[i] = *(const float4*)(A + (size_t)(row0 + lr[i]) * Dd + k0 + lc[i]);
                pb[i] = *(const float4*)(B + (size_t)(col0 + lr[i]) * Dd + k0 + lc[i]);
            }
        }

        // ---- compute on buffer b
        const uint32_t* sA = sAb[b];
        const uint32_t* sB = sBb[b];
        #pragma unroll
        for (int ks = 0; ks < 4; ks++) {
            const int kk = ks * 8;
            uint32_t af[4][4], bf[4][2];
            #pragma unroll
            for (int mt = 0; mt < 4; mt++) {
                const uint32_t* p = sA + (wm + mt * 16 + grp) * SSTRIDE + kk + tig;
                af[mt][0] = p[0];
                af[mt][1] = p[8 * SSTRIDE];
                af[mt][2] = p[4];
                af[mt][3] = p[8 * SSTRIDE + 4];
            }
            #pragma unroll
            for (int nt = 0; nt < 4; nt++) {
                const uint32_t* p = sB + (wn + nt * 8 + grp) * SSTRIDE + kk + tig;
                bf[nt][0] = p[0];
                bf[nt][1] = p[4];
            }
            #pragma unroll
            for (int mt = 0; mt < 4; mt++)
                #pragma unroll
                for (int nt = 0; nt < 4; nt++)
                    mma1688(acc[mt][nt], af[mt], bf[nt], acc[mt][nt]);
        }

        if (more) {
            uint32_t* dA = sAb[b ^ 1];
            uint32_t* dB = sBb[b ^ 1];
            #pragma unroll
            for (int i = 0; i < 4; i++) {
                uint32_t* pa2 = dA + lr[i] * SSTRIDE + lc[i];
                pa2[0] = f2tf32(pa[i].x); pa2[1] = f2tf32(pa[i].y);
                pa2[2] = f2tf32(pa[i].z); pa2[3] = f2tf32(pa[i].w);
                uint32_t* pb2 = dB + lr[i] * SSTRIDE + lc[i];
                pb2[0] = f2tf32(pb[i].x); pb2[1] = f2tf32(pb[i].y);
                pb2[2] = f2tf32(pb[i].z); pb2[3] = f2tf32(pb[i].w);
            }
        }
        __syncthreads();
    }

    // ---- epilogue: each thread owns 2 rows x 2 cols per (mt,nt) fragment
    #pragma unroll
    for (int mt = 0; mt < 4; mt++) {
        const int mloc = wm + mt * 16 + grp;   // local row, +8 for upper half
        #pragma unroll
        for (int nt = 0; nt < 4; nt++) {
            const int cn = wn + nt * 8 + 2 * tig;   // local col (pair)
            float2 v0 = make_float2(acc[mt][nt][0], acc[mt][nt][1]); // row mloc
            float2 v1 = make_float2(acc[mt][nt][2], acc[mt][nt][3]); // row mloc+8
            if (qkv_mode) {
                const int h = col0 >> 7;
                #pragma unroll
                for (int rr = 0; rr < 2; rr++) {
                    int m = row0 + mloc + rr * 8;
                    int bb = m >> 11;
                    int t = m & (Tt - 1);
                    float* dst = C + ((size_t)(bb * Hh + h) * Tt + t) * HD + cn;
                    *(float2*)dst = rr ? v1 : v0;
                }
            } else {
                const int n = col0 + cn;
                if (bias) {
                    float2 bv = *(const float2*)(bias + n);
                    v0.x += bv.x; v0.y += bv.y;
                    v1.x += bv.x; v1.y += bv.y;
                }
                *(float2*)(C + (size_t)(row0 + mloc) * Dd + n) = v0;
                *(float2*)(C + (size_t)(row0 + mloc + 8) * Dd + n) = v1;
            }
        }
    }
}

// ---------------------------------------------------------------------------
// Flash-style causal attention, fp32. 64x64 tiles, HD=128. (unchanged, proven)
// ---------------------------------------------------------------------------
#define ABM 64
#define ABN 64
#define ATTN_SMEM ((128*64 + 128*64 + 64*132 + 64*68) * 4)

__global__ __launch_bounds__(256) void attn_kernel(
    const float* __restrict__ Q, const float* __restrict__ K,
    const float* __restrict__ V, float* __restrict__ Out)
{
    extern __shared__ float sm[];
    float* Qs = sm;                 // [128][64]  ([hd][m])
    float* Ks = Qs + 128 * 64;      // [128][64]  ([hd][n])
    float* Vs = Ks + 128 * 64;      // [64][132]  ([n][hd], padded)
    float* Ps = Vs + 64 * 132;      // [64][68]   ([n][m], padded)

    const int tid = threadIdx.x;
    const int tx = tid & 15, ty = tid >> 4;
    const int qblk = (int)gridDim.x - 1 - (int)blockIdx.x;
    const int bh = blockIdx.y;
    const float* Qp = Q + ((size_t)bh * Tt + qblk * ABM) * HD;
    const float* Kp = K + (size_t)bh * Tt * HD;
    const float* Vp = V + (size_t)bh * Tt * HD;

    #pragma unroll
    for (int i = 0; i < 8; i++) {
        int f = tid * 8 + i;
        int r = f >> 5;
        int c4 = f & 31;
        float4 qv = *(const float4*)(Qp + (size_t)r * HD + c4 * 4);
        Qs[(c4 * 4 + 0) * 64 + r] = qv.x;
        Qs[(c4 * 4 + 1) * 64 + r] = qv.y;
        Qs[(c4 * 4 + 2) * 64 + r] = qv.z;
        Qs[(c4 * 4 + 3) * 64 + r] = qv.w;
    }

    float mi[4], li[4], o[4][8];
    #pragma unroll
    for (int r = 0; r < 4; r++) {
        mi[r] = -1e30f; li[r] = 0.f;
        #pragma unroll
        for (int c = 0; c < 8; c++) o[r][c] = 0.f;
    }

    const float scale = 0.08838834764831845f;
    const int qi0 = qblk * ABM + ty * 4;

    for (int jt = 0; jt <= qblk; jt++) {
        __syncthreads();
        #pragma unroll
        for (int i = 0; i < 8; i++) {
            int f = tid * 8 + i;
            int r = f >> 5;
            int c4 = f & 31;
            float4 kv = *(const float4*)(Kp + (size_t)(jt * ABN + r) * HD + c4 * 4);
            Ks[(c4 * 4 + 0) * 64 + r] = kv.x;
            Ks[(c4 * 4 + 1) * 64 + r] = kv.y;
            Ks[(c4 * 4 + 2) * 64 + r] = kv.z;
            Ks[(c4 * 4 + 3) * 64 + r] = kv.w;
            float4 vv = *(const float4*)(Vp + (size_t)(jt * ABN + r) * HD + c4 * 4);
            *(float4*)&Vs[r * 132 + c4 * 4] = vv;
        }
        __syncthreads();

        float s[4][4];
        #pragma unroll
        for (int r = 0; r < 4; r++)
            #pragma unroll
            for (int c = 0; c < 4; c++) s[r][c] = 0.f;

        #pragma unroll 4
        for (int kk = 0; kk < HD; kk++) {
            float4 qa = *(const float4*)&Qs[kk * 64 + ty * 4];
            float4 kb = *(const float4*)&Ks[kk * 64 + tx * 4];
            float aq[4] = {qa.x, qa.y, qa.z, qa.w};
            float bk[4] = {kb.x, kb.y, kb.z, kb.w};
            #pragma unroll
            for (int r = 0; r < 4; r++)
                #pragma unroll
                for (int c = 0; c < 4; c++)
                    s[r][c] = fmaf(aq[r], bk[c], s[r][c]);
        }

        const int kj0 = jt * ABN + tx * 4;
        const bool diag = (jt == qblk);
        #pragma unroll
        for (int r = 0; r < 4; r++)
            #pragma unroll
            for (int c = 0; c < 4; c++) {
                float val = s[r][c] * scale;
                if (diag && (kj0 + c > qi0 + r)) val = -1e30f;
                s[r][c] = val;
            }

        #pragma unroll
        for (int r = 0; r < 4; r++) {
            float mt = fmaxf(fmaxf(s[r][0], s[r][1]), fmaxf(s[r][2], s[r][3]));
            #pragma unroll
            for (int off = 8; off; off >>= 1)
                mt = fmaxf(mt, __shfl_xor_sync(0xffffffffu, mt, off));
            float mnew = fmaxf(mi[r], mt);
            float alpha = __expf(mi[r] - mnew);
            float lt = 0.f;
            #pragma unroll
            for (int c = 0; c < 4; c++) {
                float p = __expf(s[r][c] - mnew);
                s[r][c] = p;
                lt += p;
            }
            #pragma unroll
            for (int off = 8; off; off >>= 1)
                lt += __shfl_xor_sync(0xffffffffu, lt, off);
            li[r] = li[r] * alpha + lt;
            mi[r] = mnew;
            #pragma unroll
            for (int c = 0; c < 8; c++) o[r][c] *= alpha;
        }

        #pragma unroll
        for (int c = 0; c < 4; c++)
            *(float4*)&Ps[(tx * 4 + c) * 68 + ty * 4] =
                make_float4(s[0][c], s[1][c], s[2][c], s[3][c]);
        __syncthreads();

        #pragma unroll 2
        for (int j = 0; j < ABN; j++) {
            float4 p4 = *(const float4*)&Ps[j * 68 + ty * 4];
            float4 va = *(const float4*)&Vs[j * 132 + tx * 4];
            float4 vb = *(const float4*)&Vs[j * 132 + 64 + tx * 4];
            float pr[4] = {p4.x, p4.y, p4.z, p4.w};
            float vv[8] = {va.x, va.y, va.z, va.w, vb.x, vb.y, vb.z, vb.w};
            #pragma unroll
            for (int r = 0; r < 4; r++)
                #pragma unroll
                for (int c = 0; c < 8; c++)
                    o[r][c] = fmaf(pr[r], vv[c], o[r][c]);
        }
    }

    const int b = bh >> 4, h = bh & 15;
    float* Ob = Out + ((size_t)(b * Tt + qblk * ABM + ty * 4)) * Dd + h * HD;
    #pragma unroll
    for (int r = 0; r < 4; r++) {
        float inv = 1.0f / li[r];
        float4 w0 = make_float4(o[r][0] * inv, o[r][1] * inv, o[r][2] * inv, o[r][3] * inv);
        float4 w1 = make_float4(o[r][4] * inv, o[r][5] * inv, o[r][6] * inv, o[r][7] * inv);
        *(float4*)(Ob + (size_t)r * Dd + tx * 4) = w0;
        *(float4*)(Ob + (size_t)r * Dd + 64 + tx * 4) = w1;
    }
}

// ---------------------------------------------------------------------------
extern "C" void kernel_launch(void* const* d_in, const int* in_sizes, int n_in,
                              void* d_out, int out_size)
{
    const float* x  = (const float*)d_in[0];
    const float* Wq = (const float*)d_in[1];
    const float* Wk = (const float*)d_in[2];
    const float* Wv = (const float*)d_in[3];
    const float* Wo = (const float*)d_in[4];
    const float* bo = (const float*)d_in[5];

    float *q, *k, *v, *a;
    cudaGetSymbolAddress((void**)&q, g_q);
    cudaGetSymbolAddress((void**)&k, g_k);
    cudaGetSymbolAddress((void**)&v, g_v);
    cudaGetSymbolAddress((void**)&a, g_a);

    cudaFuncSetAttribute(tc_gemm, cudaFuncAttributeMaxDynamicSharedMemorySize, TC_SMEM);
    cudaFuncSetAttribute(attn_kernel, cudaFuncAttributeMaxDynamicSharedMemorySize, ATTN_SMEM);

    dim3 gg(Dd / TBN, Mrows / TBM);   // (16, 32)

    // QKV projections (mma.sync tf32), scattered to [B,H,T,HD]
    tc_gemm<<<gg, 256, TC_SMEM>>>(x, Wq, nullptr, q, 1);
    tc_gemm<<<gg, 256, TC_SMEM>>>(x, Wk, nullptr, k, 1);
    tc_gemm<<<gg, 256, TC_SMEM>>>(x, Wv, nullptr, v, 1);

    // Causal attention -> [B,T,D]
    attn_kernel<<<dim3(Tt / ABM, Bz * Hh), 256, ATTN_SMEM>>>(q, k, v, a);

    // Output projection + bias (mma.sync tf32)
    tc_gemm<<<gg, 256, TC_SMEM>>>(a, Wo, bo, (float*)d_out, 0);
}

// round 7
// speedup vs baseline: 2.7508x; 1.6491x over previous
#include <cuda_runtime.h>
#include <cstdint>

#define Bz 2
#define Tt 2048
#define Dd 2048
#define Hh 16
#define HD 128
#define Mrows (Bz*Tt)

// Scratch (static device globals: allocation-free, graph-capture safe)
__device__ float g_q[Bz*Hh*Tt*HD];   // [B,H,T,HD]
__device__ float g_k[Bz*Hh*Tt*HD];
__device__ float g_v[Bz*Hh*Tt*HD];
__device__ float g_a[Bz*Tt*Dd];      // attention output, [B,T,D]

__device__ __forceinline__ uint32_t f2tf32(float x) {
    uint32_t r; asm("cvt.rna.tf32.f32 %0, %1;" : "=r"(r) : "f"(x)); return r;
}
__device__ __forceinline__ void mma1688(float* d, const uint32_t* a,
                                        const uint32_t* b, const float* c) {
    asm volatile(
        "mma.sync.aligned.m16n8k8.row.col.f32.tf32.tf32.f32 "
        "{%0,%1,%2,%3}, {%4,%5,%6,%7}, {%8,%9}, {%10,%11,%12,%13};"
        : "=f"(d[0]), "=f"(d[1]), "=f"(d[2]), "=f"(d[3])
        : "r"(a[0]), "r"(a[1]), "r"(a[2]), "r"(a[3]),
          "r"(b[0]), "r"(b[1]),
          "f"(c[0]), "f"(c[1]), "f"(c[2]), "f"(c[3]));
}

// ===========================================================================
// mma.sync tf32 GEMM (NT): C[m,n] = sum_k A[m,k]*B[n,k] (+bias)  [R5, proven]
// ===========================================================================
#define TBM 128
#define TBN 128
#define TBK 32
#define NKT (Dd / TBK)            // 64
#define SSTRIDE 36
#define TILE_W (128 * SSTRIDE)
#define TC_SMEM (4 * TILE_W * 4)

__global__ __launch_bounds__(256) void tc_gemm(
    const float* __restrict__ A, const float* __restrict__ B,
    const float* __restrict__ bias, float* __restrict__ C, int qkv_mode)
{
    extern __shared__ uint32_t smw[];
    uint32_t* sAb[2] = {smw,            smw + 2 * TILE_W};
    uint32_t* sBb[2] = {smw + TILE_W,   smw + 3 * TILE_W};

    const int tid = threadIdx.x;
    const int wid = tid >> 5;
    const int lane = tid & 31;
    const int grp = lane >> 2;
    const int tig = lane & 3;
    const int wm = (wid >> 2) * 64;
    const int wn = (wid & 3) * 32;
    const int row0 = blockIdx.y * TBM;
    const int col0 = blockIdx.x * TBN;

    int lr[4], lc[4];
    #pragma unroll
    for (int i = 0; i < 4; i++) {
        int idx = tid + i * 256;
        lr[i] = idx >> 3;
        lc[i] = (idx & 7) * 4;
    }

    float acc[4][4][4];
    #pragma unroll
    for (int mt = 0; mt < 4; mt++)
        #pragma unroll
        for (int nt = 0; nt < 4; nt++)
            #pragma unroll
            for (int e = 0; e < 4; e++) acc[mt][nt][e] = 0.f;

    #pragma unroll
    for (int i = 0; i < 4; i++) {
        float4 av = *(const float4*)(A + (size_t)(row0 + lr[i]) * Dd + lc[i]);
        float4 bv = *(const float4*)(B + (size_t)(col0 + lr[i]) * Dd + lc[i]);
        uint32_t* pa = sAb[0] + lr[i] * SSTRIDE + lc[i];
        pa[0] = f2tf32(av.x); pa[1] = f2tf32(av.y); pa[2] = f2tf32(av.z); pa[3] = f2tf32(av.w);
        uint32_t* pb = sBb[0] + lr[i] * SSTRIDE + lc[i];
        pb[0] = f2tf32(bv.x); pb[1] = f2tf32(bv.y); pb[2] = f2tf32(bv.z); pb[3] = f2tf32(bv.w);
    }
    __syncthreads();

    for (int kt = 0; kt < NKT; kt++) {
        const int b = kt & 1;
        float4 pa[4], pb[4];
        const bool more = (kt + 1 < NKT);
        if (more) {
            const int k0 = (kt + 1) * TBK;
            #pragma unroll
            for (int i = 0; i < 4; i++) {
                pa[i] = *(const float4*)(A + (size_t)(row0 + lr[i]) * Dd + k0 + lc[i]);
                pb[i] = *(const float4*)(B + (size_t)(col0 + lr[i]) * Dd + k0 + lc[i]);
            }
        }

        const uint32_t* sA = sAb[b];
        const uint32_t* sB = sBb[b];
        #pragma unroll
        for (int ks = 0; ks < 4; ks++) {
            const int kk = ks * 8;
            uint32_t af[4][4], bf[4][2];
            #pragma unroll
            for (int mt = 0; mt < 4; mt++) {
                const uint32_t* p = sA + (wm + mt * 16 + grp) * SSTRIDE + kk + tig;
                af[mt][0] = p[0];
                af[mt][1] = p[8 * SSTRIDE];
                af[mt][2] = p[4];
                af[mt][3] = p[8 * SSTRIDE + 4];
            }
            #pragma unroll
            for (int nt = 0; nt < 4; nt++) {
                const uint32_t* p = sB + (wn + nt * 8 + grp) * SSTRIDE + kk + tig;
                bf[nt][0] = p[0];
                bf[nt][1] = p[4];
            }
            #pragma unroll
            for (int mt = 0; mt < 4; mt++)
                #pragma unroll
                for (int nt = 0; nt < 4; nt++)
                    mma1688(acc[mt][nt], af[mt], bf[nt], acc[mt][nt]);
        }

        if (more) {
            uint32_t* dA = sAb[b ^ 1];
            uint32_t* dB = sBb[b ^ 1];
            #pragma unroll
            for (int i = 0; i < 4; i++) {
                uint32_t* pa2 = dA + lr[i] * SSTRIDE + lc[i];
                pa2[0] = f2tf32(pa[i].x); pa2[1] = f2tf32(pa[i].y);
                pa2[2] = f2tf32(pa[i].z); pa2[3] = f2tf32(pa[i].w);
                uint32_t* pb2 = dB + lr[i] * SSTRIDE + lc[i];
                pb2[0] = f2tf32(pb[i].x); pb2[1] = f2tf32(pb[i].y);
                pb2[2] = f2tf32(pb[i].z); pb2[3] = f2tf32(pb[i].w);
            }
        }
        __syncthreads();
    }

    #pragma unroll
    for (int mt = 0; mt < 4; mt++) {
        const int mloc = wm + mt * 16 + grp;
        #pragma unroll
        for (int nt = 0; nt < 4; nt++) {
            const int cn = wn + nt * 8 + 2 * tig;
            float2 v0 = make_float2(acc[mt][nt][0], acc[mt][nt][1]);
            float2 v1 = make_float2(acc[mt][nt][2], acc[mt][nt][3]);
            if (qkv_mode) {
                const int h = col0 >> 7;
                #pragma unroll
                for (int rr = 0; rr < 2; rr++) {
                    int m = row0 + mloc + rr * 8;
                    int bb = m >> 11;
                    int t = m & (Tt - 1);
                    float* dst = C + ((size_t)(bb * Hh + h) * Tt + t) * HD + cn;
                    *(float2*)dst = rr ? v1 : v0;
                }
            } else {
                const int n = col0 + cn;
                if (bias) {
                    float2 bv = *(const float2*)(bias + n);
                    v0.x += bv.x; v0.y += bv.y;
                    v1.x += bv.x; v1.y += bv.y;
                }
                *(float2*)(C + (size_t)(row0 + mloc) * Dd + n) = v0;
                *(float2*)(C + (size_t)(row0 + mloc + 8) * Dd + n) = v1;
            }
        }
    }
}

// ===========================================================================
// Tensor-core causal flash attention (mma.sync tf32)
// CTA: 128 q-rows x 64-key tiles. 8 warps, each owns a 16-row band.
// Warp-local online softmax (rows never cross warps).
// ===========================================================================
#define QS_STR 132
#define KS_STR 132
#define VS_STR 136
#define PS_STR 68
#define KS_OFF (128 * QS_STR)
#define VS_OFF (KS_OFF + 64 * KS_STR)
#define PS_OFF (VS_OFF + 64 * VS_STR)
#define ATN_SMEM ((PS_OFF + 128 * PS_STR) * 4)   // 171008 B

__global__ __launch_bounds__(256) void attn_tc(
    const float* __restrict__ Q, const float* __restrict__ K,
    const float* __restrict__ V, float* __restrict__ Out)
{
    extern __shared__ uint32_t sw[];
    uint32_t* Qs = sw;             // [128][132]
    uint32_t* Ks = sw + KS_OFF;    // [64][132]
    uint32_t* Vs = sw + VS_OFF;    // [64][136]
    uint32_t* Ps = sw + PS_OFF;    // [128][68]

    const int tid = threadIdx.x;
    const int wid = tid >> 5;
    const int lane = tid & 31;
    const int grp = lane >> 2;     // 0..7
    const int tig = lane & 3;      // 0..3
    const int wm = wid * 16;       // warp row band
    const int qblk = (int)gridDim.x - 1 - (int)blockIdx.x;   // longest first
    const int bh = blockIdx.y;
    const float* Qp = Q + ((size_t)bh * Tt + qblk * 128) * HD;
    const float* Kp = K + (size_t)bh * Tt * HD;
    const float* Vp = V + (size_t)bh * Tt * HD;
    const float scale = 0.08838834764831845f;   // 1/sqrt(128)

    // Stage Q tile (128x128) -> Qs tf32
    #pragma unroll
    for (int i = 0; i < 16; i++) {
        int idx = tid + i * 256;
        int r = idx >> 5, c4 = idx & 31;
        float4 v = *(const float4*)(Qp + (size_t)r * HD + c4 * 4);
        *(uint4*)(Qs + r * QS_STR + c4 * 4) =
            make_uint4(f2tf32(v.x), f2tf32(v.y), f2tf32(v.z), f2tf32(v.w));
    }

    float o[16][4];
    #pragma unroll
    for (int nf = 0; nf < 16; nf++)
        #pragma unroll
        for (int e = 0; e < 4; e++) o[nf][e] = 0.f;
    float mi0 = -1e30f, mi1 = -1e30f, li0 = 0.f, li1 = 0.f;

    const int jmax = 2 * qblk + 1;
    const int r0g = qblk * 128 + wm + grp;     // global row of acc elems 0,1
    const int r1g = r0g + 8;                   // global row of acc elems 2,3

    for (int jt = 0; jt <= jmax; jt++) {
        __syncthreads();     // prior QK/PV reads of Ks/Vs done
        // Stage K/V tile (64x128 each)
        #pragma unroll
        for (int i = 0; i < 8; i++) {
            int idx = tid + i * 256;
            int r = idx >> 5, c4 = idx & 31;
            float4 kv = *(const float4*)(Kp + (size_t)(jt * 64 + r) * HD + c4 * 4);
            *(uint4*)(Ks + r * KS_STR + c4 * 4) =
                make_uint4(f2tf32(kv.x), f2tf32(kv.y), f2tf32(kv.z), f2tf32(kv.w));
            float4 vv = *(const float4*)(Vp + (size_t)(jt * 64 + r) * HD + c4 * 4);
            *(uint4*)(Vs + r * VS_STR + c4 * 4) =
                make_uint4(f2tf32(vv.x), f2tf32(vv.y), f2tf32(vv.z), f2tf32(vv.w));
        }
        __syncthreads();

        // ---- S = Q K^T : warp computes [16 x 64]
        float s[8][4];
        #pragma unroll
        for (int nf = 0; nf < 8; nf++)
            #pragma unroll
            for (int e = 0; e < 4; e++) s[nf][e] = 0.f;

        #pragma unroll
        for (int ks = 0; ks < 16; ks++) {
            uint32_t a[4];
            const uint32_t* qp = Qs + (wm + grp) * QS_STR + ks * 8 + tig;
            a[0] = qp[0];
            a[1] = qp[8 * QS_STR];
            a[2] = qp[4];
            a[3] = qp[8 * QS_STR + 4];
            #pragma unroll
            for (int nf = 0; nf < 8; nf++) {
                uint32_t b[2];
                const uint32_t* kp = Ks + (nf * 8 + grp) * KS_STR + ks * 8 + tig;
                b[0] = kp[0];
                b[1] = kp[4];
                mma1688(s[nf], a, b, s[nf]);
            }
        }

        // scale + causal mask (only diagonal key-blocks need it)
        #pragma unroll
        for (int nf = 0; nf < 8; nf++)
            #pragma unroll
            for (int e = 0; e < 4; e++) s[nf][e] *= scale;
        if (jt >= 2 * qblk) {
            #pragma unroll
            for (int nf = 0; nf < 8; nf++) {
                int c0 = jt * 64 + nf * 8 + 2 * tig;
                if (c0     > r0g) s[nf][0] = -1e30f;
                if (c0 + 1 > r0g) s[nf][1] = -1e30f;
                if (c0     > r1g) s[nf][2] = -1e30f;
                if (c0 + 1 > r1g) s[nf][3] = -1e30f;
            }
        }

        // ---- warp-local online softmax (rows r0, r1)
        float m0 = -1e30f, m1 = -1e30f;
        #pragma unroll
        for (int nf = 0; nf < 8; nf++) {
            m0 = fmaxf(m0, fmaxf(s[nf][0], s[nf][1]));
            m1 = fmaxf(m1, fmaxf(s[nf][2], s[nf][3]));
        }
        m0 = fmaxf(m0, __shfl_xor_sync(0xffffffffu, m0, 1));
        m0 = fmaxf(m0, __shfl_xor_sync(0xffffffffu, m0, 2));
        m1 = fmaxf(m1, __shfl_xor_sync(0xffffffffu, m1, 1));
        m1 = fmaxf(m1, __shfl_xor_sync(0xffffffffu, m1, 2));
        float mn0 = fmaxf(mi0, m0), mn1 = fmaxf(mi1, m1);
        float al0 = __expf(mi0 - mn0), al1 = __expf(mi1 - mn1);
        float sum0 = 0.f, sum1 = 0.f;
        #pragma unroll
        for (int nf = 0; nf < 8; nf++) {
            s[nf][0] = __expf(s[nf][0] - mn0);
            s[nf][1] = __expf(s[nf][1] - mn0);
            s[nf][2] = __expf(s[nf][2] - mn1);
            s[nf][3] = __expf(s[nf][3] - mn1);
            sum0 += s[nf][0] + s[nf][1];
            sum1 += s[nf][2] + s[nf][3];
        }
        sum0 += __shfl_xor_sync(0xffffffffu, sum0, 1);
        sum0 += __shfl_xor_sync(0xffffffffu, sum0, 2);
        sum1 += __shfl_xor_sync(0xffffffffu, sum1, 1);
        sum1 += __shfl_xor_sync(0xffffffffu, sum1, 2);
        li0 = li0 * al0 + sum0;  mi0 = mn0;
        li1 = li1 * al1 + sum1;  mi1 = mn1;
        #pragma unroll
        for (int nf = 0; nf < 16; nf++) {
            o[nf][0] *= al0; o[nf][1] *= al0;
            o[nf][2] *= al1; o[nf][3] *= al1;
        }

        // ---- stage P (tf32) to warp-private Ps rows
        #pragma unroll
        for (int nf = 0; nf < 8; nf++) {
            uint32_t* p0 = Ps + (wm + grp) * PS_STR + nf * 8 + 2 * tig;
            p0[0] = f2tf32(s[nf][0]); p0[1] = f2tf32(s[nf][1]);
            uint32_t* p1 = Ps + (wm + grp + 8) * PS_STR + nf * 8 + 2 * tig;
            p1[0] = f2tf32(s[nf][2]); p1[1] = f2tf32(s[nf][3]);
        }
        __syncwarp();

        // ---- O += P V  (K=64 keys, N=128 hd)
        #pragma unroll
        for (int ks = 0; ks < 8; ks++) {
            uint32_t a[4];
            const uint32_t* pp = Ps + (wm + grp) * PS_STR + ks * 8 + tig;
            a[0] = pp[0];
            a[1] = pp[8 * PS_STR];
            a[2] = pp[4];
            a[3] = pp[8 * PS_STR + 4];
            #pragma unroll
            for (int nf = 0; nf < 16; nf++) {
                uint32_t b[2];
                const uint32_t* vp = Vs + (ks * 8 + tig) * VS_STR + nf * 8 + grp;
                b[0] = vp[0];
                b[1] = vp[4 * VS_STR];
                mma1688(o[nf], a, b, o[nf]);
            }
        }
        __syncwarp();   // Ps reads done before next jt overwrites
    }

    // ---- epilogue: normalize, write [B,T,D]
    const int b = bh >> 4, h = bh & 15;
    const int t0 = qblk * 128 + wm + grp;
    float inv0 = 1.0f / li0, inv1 = 1.0f / li1;
    float* O0 = Out + ((size_t)(b * Tt + t0)) * Dd + h * HD;
    #pragma unroll
    for (int nf = 0; nf < 16; nf++) {
        int c = nf * 8 + 2 * tig;
        *(float2*)(O0 + c) = make_float2(o[nf][0] * inv0, o[nf][1] * inv0);
        *(float2*)(O0 + (size_t)8 * Dd + c) = make_float2(o[nf][2] * inv1, o[nf][3] * inv1);
    }
}

// ---------------------------------------------------------------------------
extern "C" void kernel_launch(void* const* d_in, const int* in_sizes, int n_in,
                              void* d_out, int out_size)
{
    const float* x  = (const float*)d_in[0];
    const float* Wq = (const float*)d_in[1];
    const float* Wk = (const float*)d_in[2];
    const float* Wv = (const float*)d_in[3];
    const float* Wo = (const float*)d_in[4];
    const float* bo = (const float*)d_in[5];

    float *q, *k, *v, *a;
    cudaGetSymbolAddress((void**)&q, g_q);
    cudaGetSymbolAddress((void**)&k, g_k);
    cudaGetSymbolAddress((void**)&v, g_v);
    cudaGetSymbolAddress((void**)&a, g_a);

    cudaFuncSetAttribute(tc_gemm, cudaFuncAttributeMaxDynamicSharedMemorySize, TC_SMEM);
    cudaFuncSetAttribute(attn_tc, cudaFuncAttributeMaxDynamicSharedMemorySize, ATN_SMEM);

    dim3 gg(Dd / TBN, Mrows / TBM);   // (16, 32)

    // QKV projections (mma.sync tf32), scattered to [B,H,T,HD]
    tc_gemm<<<gg, 256, TC_SMEM>>>(x, Wq, nullptr, q, 1);
    tc_gemm<<<gg, 256, TC_SMEM>>>(x, Wk, nullptr, k, 1);
    tc_gemm<<<gg, 256, TC_SMEM>>>(x, Wv, nullptr, v, 1);

    // Tensor-core causal attention -> [B,T,D]
    attn_tc<<<dim3(Tt / 128, Bz * Hh), 256, ATN_SMEM>>>(q, k, v, a);

    // Output projection + bias (mma.sync tf32)
    tc_gemm<<<gg, 256, TC_SMEM>>>(a, Wo, bo, (float*)d_out, 0);
}

// round 9
// speedup vs baseline: 3.2824x; 1.1932x over previous
#include <cuda_runtime.h>
#include <cstdint>

#define Bz 2
#define Tt 2048
#define Dd 2048
#define Hh 16
#define HD 128
#define Mrows (Bz*Tt)

// Scratch (static device globals: allocation-free, graph-capture safe)
__device__ float g_q[Bz*Hh*Tt*HD];   // [B,H,T,HD]
__device__ float g_k[Bz*Hh*Tt*HD];
__device__ float g_v[Bz*Hh*Tt*HD];
__device__ float g_a[Bz*Tt*Dd];      // attention output, [B,T,D]

__device__ __forceinline__ uint32_t f2tf32(float x) {
    uint32_t r; asm("cvt.rna.tf32.f32 %0, %1;" : "=r"(r) : "f"(x)); return r;
}
__device__ __forceinline__ void mma1688(float* d, const uint32_t* a,
                                        const uint32_t* b, const float* c) {
    asm volatile(
        "mma.sync.aligned.m16n8k8.row.col.f32.tf32.tf32.f32 "
        "{%0,%1,%2,%3}, {%4,%5,%6,%7}, {%8,%9}, {%10,%11,%12,%13};"
        : "=f"(d[0]), "=f"(d[1]), "=f"(d[2]), "=f"(d[3])
        : "r"(a[0]), "r"(a[1]), "r"(a[2]), "r"(a[3]),
          "r"(b[0]), "r"(b[1]),
          "f"(c[0]), "f"(c[1]), "f"(c[2]), "f"(c[3]));
}
__device__ __forceinline__ uint32_t smem_u32(const void* p) {
    uint32_t a;
    asm("{ .reg .u64 t; cvta.to.shared.u64 t, %1; cvt.u32.u64 %0, t; }" : "=r"(a) : "l"(p));
    return a;
}
__device__ __forceinline__ void cp16(uint32_t dst, const void* src) {
    asm volatile("cp.async.cg.shared.global [%0], [%1], 16;" :: "r"(dst), "l"(src));
}

// ===========================================================================
// mma.sync tf32 GEMM v2 (NT): C[m,n] = sum_k A[m,k]*B[n,k] (+bias)
// cp.async double-buffered raw-fp32 smem; tf32 cvt on fragment load.
// 2 CTAs/SM (launch_bounds 256,2). CTA 128x128, BK=32, 8 warps 64x32.
// ===========================================================================
#define TBM 128
#define TBN 128
#define TBK 32
#define NKT (Dd / TBK)            // 64
#define SSTRIDE 36                // 32 + 4 pad words (144 B rows, 16B aligned)
#define TILE_W (128 * SSTRIDE)
#define TC_SMEM (4 * TILE_W * 4)  // 73728 B -> 2 CTAs/SM

__global__ __launch_bounds__(256, 2) void tc_gemm(
    const float* __restrict__ A, const float* __restrict__ B,
    const float* __restrict__ bias, float* __restrict__ C, int qkv_mode)
{
    extern __shared__ float smf[];
    float* sAb[2] = {smf,            smf + 2 * TILE_W};
    float* sBb[2] = {smf + TILE_W,   smf + 3 * TILE_W};
    const uint32_t sbase = smem_u32(smf);

    const int tid = threadIdx.x;
    const int wid = tid >> 5;
    const int lane = tid & 31;
    const int grp = lane >> 2;
    const int tig = lane & 3;
    const int wm = (wid >> 2) * 64;
    const int wn = (wid & 3) * 32;
    const int row0 = blockIdx.y * TBM;
    const int col0 = blockIdx.x * TBN;

    // per-thread copy coords: 4 x 16B per operand per tile
    int lr[4], lc[4];
    #pragma unroll
    for (int i = 0; i < 4; i++) {
        int idx = tid + i * 256;
        lr[i] = idx >> 3;          // row 0..127
        lc[i] = (idx & 7) * 4;     // col 0,4,...,28
    }

    float acc[4][4][4];
    #pragma unroll
    for (int mt = 0; mt < 4; mt++)
        #pragma unroll
        for (int nt = 0; nt < 4; nt++)
            #pragma unroll
            for (int e = 0; e < 4; e++) acc[mt][nt][e] = 0.f;

    // ---- prologue: async-copy tile 0 into buffer 0
    #pragma unroll
    for (int i = 0; i < 4; i++) {
        uint32_t so = (uint32_t)((lr[i] * SSTRIDE + lc[i]) * 4);
        cp16(sbase + so, A + (size_t)(row0 + lr[i]) * Dd + lc[i]);
        cp16(sbase + TILE_W * 4 + so, B + (size_t)(col0 + lr[i]) * Dd + lc[i]);
    }
    asm volatile("cp.async.commit_group;");

    for (int kt = 0; kt < NKT; kt++) {
        const int b = kt & 1;
        const bool more = (kt + 1 < NKT);
        if (more) {
            const int k0 = (kt + 1) * TBK;
            const uint32_t abuf = sbase + (uint32_t)(b ^ 1) * 2u * TILE_W * 4u;
            #pragma unroll
            for (int i = 0; i < 4; i++) {
                uint32_t so = (uint32_t)((lr[i] * SSTRIDE + lc[i]) * 4);
                cp16(abuf + so, A + (size_t)(row0 + lr[i]) * Dd + k0 + lc[i]);
                cp16(abuf + TILE_W * 4 + so, B + (size_t)(col0 + lr[i]) * Dd + k0 + lc[i]);
            }
            asm volatile("cp.async.commit_group;");
            asm volatile("cp.async.wait_group 1;");
        } else {
            asm volatile("cp.async.wait_group 0;");
        }
        __syncthreads();

        // ---- compute on buffer b (cvt to tf32 on fragment load)
        const float* sA = sAb[b];
        const float* sB = sBb[b];
        #pragma unroll
        for (int ks = 0; ks < 4; ks++) {
            const int kk = ks * 8;
            uint32_t af[4][4], bf[4][2];
            #pragma unroll
            for (int mt = 0; mt < 4; mt++) {
                const float* p = sA + (wm + mt * 16 + grp) * SSTRIDE + kk + tig;
                af[mt][0] = f2tf32(p[0]);
                af[mt][1] = f2tf32(p[8 * SSTRIDE]);
                af[mt][2] = f2tf32(p[4]);
                af[mt][3] = f2tf32(p[8 * SSTRIDE + 4]);
            }
            #pragma unroll
            for (int nt = 0; nt < 4; nt++) {
                const float* p = sB + (wn + nt * 8 + grp) * SSTRIDE + kk + tig;
                bf[nt][0] = f2tf32(p[0]);
                bf[nt][1] = f2tf32(p[4]);
            }
            #pragma unroll
            for (int mt = 0; mt < 4; mt++)
                #pragma unroll
                for (int nt = 0; nt < 4; nt++)
                    mma1688(acc[mt][nt], af[mt], bf[nt], acc[mt][nt]);
        }
        __syncthreads();
    }

    // ---- epilogue
    #pragma unroll
    for (int mt = 0; mt < 4; mt++) {
        const int mloc = wm + mt * 16 + grp;
        #pragma unroll
        for (int nt = 0; nt < 4; nt++) {
            const int cn = wn + nt * 8 + 2 * tig;
            float2 v0 = make_float2(acc[mt][nt][0], acc[mt][nt][1]);
            float2 v1 = make_float2(acc[mt][nt][2], acc[mt][nt][3]);
            if (qkv_mode) {
                const int h = col0 >> 7;
                #pragma unroll
                for (int rr = 0; rr < 2; rr++) {
                    int m = row0 + mloc + rr * 8;
                    int bb = m >> 11;
                    int t = m & (Tt - 1);
                    float* dst = C + ((size_t)(bb * Hh + h) * Tt + t) * HD + cn;
                    *(float2*)dst = rr ? v1 : v0;
                }
            } else {
                const int n = col0 + cn;
                if (bias) {
                    float2 bv = *(const float2*)(bias + n);
                    v0.x += bv.x; v0.y += bv.y;
                    v1.x += bv.x; v1.y += bv.y;
                }
                *(float2*)(C + (size_t)(row0 + mloc) * Dd + n) = v0;
                *(float2*)(C + (size_t)(row0 + mloc + 8) * Dd + n) = v1;
            }
        }
    }
}

// ===========================================================================
// Tensor-core causal flash attention (mma.sync tf32)  [R7, proven — unchanged]
// ===========================================================================
#define QS_STR 132
#define KS_STR 132
#define VS_STR 136
#define PS_STR 68
#define KS_OFF (128 * QS_STR)
#define VS_OFF (KS_OFF + 64 * KS_STR)
#define PS_OFF (VS_OFF + 64 * VS_STR)
#define ATN_SMEM ((PS_OFF + 128 * PS_STR) * 4)   // 171008 B

__global__ __launch_bounds__(256) void attn_tc(
    const float* __restrict__ Q, const float* __restrict__ K,
    const float* __restrict__ V, float* __restrict__ Out)
{
    extern __shared__ uint32_t sw[];
    uint32_t* Qs = sw;             // [128][132]
    uint32_t* Ks = sw + KS_OFF;    // [64][132]
    uint32_t* Vs = sw + VS_OFF;    // [64][136]
    uint32_t* Ps = sw + PS_OFF;    // [128][68]

    const int tid = threadIdx.x;
    const int wid = tid >> 5;
    const int lane = tid & 31;
    const int grp = lane >> 2;     // 0..7
    const int tig = lane & 3;      // 0..3
    const int wm = wid * 16;       // warp row band
    const int qblk = (int)gridDim.x - 1 - (int)blockIdx.x;   // longest first
    const int bh = blockIdx.y;
    const float* Qp = Q + ((size_t)bh * Tt + qblk * 128) * HD;
    const float* Kp = K + (size_t)bh * Tt * HD;
    const float* Vp = V + (size_t)bh * Tt * HD;
    const float scale = 0.08838834764831845f;   // 1/sqrt(128)

    // Stage Q tile (128x128) -> Qs tf32
    #pragma unroll
    for (int i = 0; i < 16; i++) {
        int idx = tid + i * 256;
        int r = idx >> 5, c4 = idx & 31;
        float4 v = *(const float4*)(Qp + (size_t)r * HD + c4 * 4);
        *(uint4*)(Qs + r * QS_STR + c4 * 4) =
            make_uint4(f2tf32(v.x), f2tf32(v.y), f2tf32(v.z), f2tf32(v.w));
    }

    float o[16][4];
    #pragma unroll
    for (int nf = 0; nf < 16; nf++)
        #pragma unroll
        for (int e = 0; e < 4; e++) o[nf][e] = 0.f;
    float mi0 = -1e30f, mi1 = -1e30f, li0 = 0.f, li1 = 0.f;

    const int jmax = 2 * qblk + 1;
    const int r0g = qblk * 128 + wm + grp;     // global row of acc elems 0,1
    const int r1g = r0g + 8;                   // global row of acc elems 2,3

    for (int jt = 0; jt <= jmax; jt++) {
        __syncthreads();     // prior QK/PV reads of Ks/Vs done
        // Stage K/V tile (64x128 each)
        #pragma unroll
        for (int i = 0; i < 8; i++) {
            int idx = tid + i * 256;
            int r = idx >> 5, c4 = idx & 31;
            float4 kv = *(const float4*)(Kp + (size_t)(jt * 64 + r) * HD + c4 * 4);
            *(uint4*)(Ks + r * KS_STR + c4 * 4) =
                make_uint4(f2tf32(kv.x), f2tf32(kv.y), f2tf32(kv.z), f2tf32(kv.w));
            float4 vv = *(const float4*)(Vp + (size_t)(jt * 64 + r) * HD + c4 * 4);
            *(uint4*)(Vs + r * VS_STR + c4 * 4) =
                make_uint4(f2tf32(vv.x), f2tf32(vv.y), f2tf32(vv.z), f2tf32(vv.w));
        }
        __syncthreads();

        // ---- S = Q K^T : warp computes [16 x 64]
        float s[8][4];
        #pragma unroll
        for (int nf = 0; nf < 8; nf++)
            #pragma unroll
            for (int e = 0; e < 4; e++) s[nf][e] = 0.f;

        #pragma unroll
        for (int ks = 0; ks < 16; ks++) {
            uint32_t a[4];
            const uint32_t* qp = Qs + (wm + grp) * QS_STR + ks * 8 + tig;
            a[0] = qp[0];
            a[1] = qp[8 * QS_STR];
            a[2] = qp[4];
            a[3] = qp[8 * QS_STR + 4];
            #pragma unroll
            for (int nf = 0; nf < 8; nf++) {
                uint32_t b[2];
                const uint32_t* kp = Ks + (nf * 8 + grp) * KS_STR + ks * 8 + tig;
                b[0] = kp[0];
                b[1] = kp[4];
                mma1688(s[nf], a, b, s[nf]);
            }
        }

        // scale + causal mask (only diagonal key-blocks need it)
        #pragma unroll
        for (int nf = 0; nf < 8; nf++)
            #pragma unroll
            for (int e = 0; e < 4; e++) s[nf][e] *= scale;
        if (jt >= 2 * qblk) {
            #pragma unroll
            for (int nf = 0; nf < 8; nf++) {
                int c0 = jt * 64 + nf * 8 + 2 * tig;
                if (c0     > r0g) s[nf][0] = -1e30f;
                if (c0 + 1 > r0g) s[nf][1] = -1e30f;
                if (c0     > r1g) s[nf][2] = -1e30f;
                if (c0 + 1 > r1g) s[nf][3] = -1e30f;
            }
        }

        // ---- warp-local online softmax (rows r0, r1)
        float m0 = -1e30f, m1 = -1e30f;
        #pragma unroll
        for (int nf = 0; nf < 8; nf++) {
            m0 = fmaxf(m0, fmaxf(s[nf][0], s[nf][1]));
            m1 = fmaxf(m1, fmaxf(s[nf][2], s[nf][3]));
        }
        m0 = fmaxf(m0, __shfl_xor_sync(0xffffffffu, m0, 1));
        m0 = fmaxf(m0, __shfl_xor_sync(0xffffffffu, m0, 2));
        m1 = fmaxf(m1, __shfl_xor_sync(0xffffffffu, m1, 1));
        m1 = fmaxf(m1, __shfl_xor_sync(0xffffffffu, m1, 2));
        float mn0 = fmaxf(mi0, m0), mn1 = fmaxf(mi1, m1);
        float al0 = __expf(mi0 - mn0), al1 = __expf(mi1 - mn1);
        float sum0 = 0.f, sum1 = 0.f;
        #pragma unroll
        for (int nf = 0; nf < 8; nf++) {
            s[nf][0] = __expf(s[nf][0] - mn0);
            s[nf][1] = __expf(s[nf][1] - mn0);
            s[nf][2] = __expf(s[nf][2] - mn1);
            s[nf][3] = __expf(s[nf][3] - mn1);
            sum0 += s[nf][0] + s[nf][1];
            sum1 += s[nf][2] + s[nf][3];
        }
        sum0 += __shfl_xor_sync(0xffffffffu, sum0, 1);
        sum0 += __shfl_xor_sync(0xffffffffu, sum0, 2);
        sum1 += __shfl_xor_sync(0xffffffffu, sum1, 1);
        sum1 += __shfl_xor_sync(0xffffffffu, sum1, 2);
        li0 = li0 * al0 + sum0;  mi0 = mn0;
        li1 = li1 * al1 + sum1;  mi1 = mn1;
        #pragma unroll
        for (int nf = 0; nf < 16; nf++) {
            o[nf][0] *= al0; o[nf][1] *= al0;
            o[nf][2] *= al1; o[nf][3] *= al1;
        }

        // ---- stage P (tf32) to warp-private Ps rows
        #pragma unroll
        for (int nf = 0; nf < 8; nf++) {
            uint32_t* p0 = Ps + (wm + grp) * PS_STR + nf * 8 + 2 * tig;
            p0[0] = f2tf32(s[nf][0]); p0[1] = f2tf32(s[nf][1]);
            uint32_t* p1 = Ps + (wm + grp + 8) * PS_STR + nf * 8 + 2 * tig;
            p1[0] = f2tf32(s[nf][2]); p1[1] = f2tf32(s[nf][3]);
        }
        __syncwarp();

        // ---- O += P V  (K=64 keys, N=128 hd)
        #pragma unroll
        for (int ks = 0; ks < 8; ks++) {
            uint32_t a[4];
            const uint32_t* pp = Ps + (wm + grp) * PS_STR + ks * 8 + tig;
            a[0] = pp[0];
            a[1] = pp[8 * PS_STR];
            a[2] = pp[4];
            a[3] = pp[8 * PS_STR + 4];
            #pragma unroll
            for (int nf = 0; nf < 16; nf++) {
                uint32_t b[2];
                const uint32_t* vp = Vs + (ks * 8 + tig) * VS_STR + nf * 8 + grp;
                b[0] = vp[0];
                b[1] = vp[4 * VS_STR];
                mma1688(o[nf], a, b, o[nf]);
            }
        }
        __syncwarp();   // Ps reads done before next jt overwrites
    }

    // ---- epilogue: normalize, write [B,T,D]
    const int b = bh >> 4, h = bh & 15;
    const int t0 = qblk * 128 + wm + grp;
    float inv0 = 1.0f / li0, inv1 = 1.0f / li1;
    float* O0 = Out + ((size_t)(b * Tt + t0)) * Dd + h * HD;
    #pragma unroll
    for (int nf = 0; nf < 16; nf++) {
        int c = nf * 8 + 2 * tig;
        *(float2*)(O0 + c) = make_float2(o[nf][0] * inv0, o[nf][1] * inv0);
        *(float2*)(O0 + (size_t)8 * Dd + c) = make_float2(o[nf][2] * inv1, o[nf][3] * inv1);
    }
}

// ---------------------------------------------------------------------------
extern "C" void kernel_launch(void* const* d_in, const int* in_sizes, int n_in,
                              void* d_out, int out_size)
{
    const float* x  = (const float*)d_in[0];
    const float* Wq = (const float*)d_in[1];
    const float* Wk = (const float*)d_in[2];
    const float* Wv = (const float*)d_in[3];
    const float* Wo = (const float*)d_in[4];
    const float* bo = (const float*)d_in[5];

    float *q, *k, *v, *a;
    cudaGetSymbolAddress((void**)&q, g_q);
    cudaGetSymbolAddress((void**)&k, g_k);
    cudaGetSymbolAddress((void**)&v, g_v);
    cudaGetSymbolAddress((void**)&a, g_a);

    cudaFuncSetAttribute(tc_gemm, cudaFuncAttributeMaxDynamicSharedMemorySize, TC_SMEM);
    cudaFuncSetAttribute(attn_tc, cudaFuncAttributeMaxDynamicSharedMemorySize, ATN_SMEM);

    dim3 gg(Dd / TBN, Mrows / TBM);   // (16, 32)

    // QKV projections (mma.sync tf32 + cp.async), scattered to [B,H,T,HD]
    tc_gemm<<<gg, 256, TC_SMEM>>>(x, Wq, nullptr, q, 1);
    tc_gemm<<<gg, 256, TC_SMEM>>>(x, Wk, nullptr, k, 1);
    tc_gemm<<<gg, 256, TC_SMEM>>>(x, Wv, nullptr, v, 1);

    // Tensor-core causal attention -> [B,T,D]
    attn_tc<<<dim3(Tt / 128, Bz * Hh), 256, ATN_SMEM>>>(q, k, v, a);

    // Output projection + bias (mma.sync tf32 + cp.async)
    tc_gemm<<<gg, 256, TC_SMEM>>>(a, Wo, bo, (float*)d_out, 0);
}

// round 10
// speedup vs baseline: 5.4152x; 1.6498x over previous
#include <cuda_runtime.h>
#include <cuda_fp16.h>
#include <cstdint>

#define Bz 2
#define Tt 2048
#define Dd 2048
#define Hh 16
#define HD 128
#define Mrows (Bz*Tt)

// Scratch (static device globals: allocation-free, graph-capture safe)
__device__ float  g_q[Bz*Hh*Tt*HD];     // [B,H,T,HD] fp32
__device__ float  g_k[Bz*Hh*Tt*HD];
__device__ float  g_v[Bz*Hh*Tt*HD];
__device__ __half g_xh[Mrows*Dd];       // x in fp16
__device__ __half g_wh[4*Dd*Dd];        // Wq|Wk|Wv|Wo in fp16
__device__ __half g_ah[Mrows*Dd];       // attention output [B,T,D] fp16

__device__ __forceinline__ uint32_t f2tf32(float x) {
    uint32_t r; asm("cvt.rna.tf32.f32 %0, %1;" : "=r"(r) : "f"(x)); return r;
}
__device__ __forceinline__ void mma1688(float* d, const uint32_t* a,
                                        const uint32_t* b, const float* c) {
    asm volatile(
        "mma.sync.aligned.m16n8k8.row.col.f32.tf32.tf32.f32 "
        "{%0,%1,%2,%3}, {%4,%5,%6,%7}, {%8,%9}, {%10,%11,%12,%13};"
        : "=f"(d[0]), "=f"(d[1]), "=f"(d[2]), "=f"(d[3])
        : "r"(a[0]), "r"(a[1]), "r"(a[2]), "r"(a[3]),
          "r"(b[0]), "r"(b[1]),
          "f"(c[0]), "f"(c[1]), "f"(c[2]), "f"(c[3]));
}
__device__ __forceinline__ void mma16816h(float* d, const uint32_t* a,
                                          const uint32_t* b, const float* c) {
    asm volatile(
        "mma.sync.aligned.m16n8k16.row.col.f32.f16.f16.f32 "
        "{%0,%1,%2,%3}, {%4,%5,%6,%7}, {%8,%9}, {%10,%11,%12,%13};"
        : "=f"(d[0]), "=f"(d[1]), "=f"(d[2]), "=f"(d[3])
        : "r"(a[0]), "r"(a[1]), "r"(a[2]), "r"(a[3]),
          "r"(b[0]), "r"(b[1]),
          "f"(c[0]), "f"(c[1]), "f"(c[2]), "f"(c[3]));
}
__device__ __forceinline__ uint32_t smem_u32(const void* p) {
    uint32_t a;
    asm("{ .reg .u64 t; cvta.to.shared.u64 t, %1; cvt.u32.u64 %0, t; }" : "=r"(a) : "l"(p));
    return a;
}
__device__ __forceinline__ void cp16(uint32_t dst, const void* src) {
    asm volatile("cp.async.cg.shared.global [%0], [%1], 16;" :: "r"(dst), "l"(src));
}

// ===========================================================================
// fp32 -> fp16 conversion pre-pass. blockIdx.y selects tensor:
// 0: x -> g_xh ; 1..4: Wq/Wk/Wv/Wo -> g_wh slices.
// ===========================================================================
__global__ __launch_bounds__(256) void cvt_fp16(
    const float* __restrict__ x,
    const float* __restrict__ wq, const float* __restrict__ wk,
    const float* __restrict__ wv, const float* __restrict__ wo)
{
    const int sel = blockIdx.y;
    const float* src = (sel == 0) ? x : (sel == 1) ? wq : (sel == 2) ? wk
                       : (sel == 3) ? wv : wo;
    __half* dst = (sel == 0) ? g_xh : g_wh + (size_t)(sel - 1) * Dd * Dd;
    const int n = (sel == 0) ? Mrows * Dd : Dd * Dd;
    const int stride = gridDim.x * blockDim.x * 4;
    for (int i = (blockIdx.x * blockDim.x + threadIdx.x) * 4; i < n; i += stride) {
        float4 v = *(const float4*)(src + i);
        __half2 h0 = __floats2half2_rn(v.x, v.y);
        __half2 h1 = __floats2half2_rn(v.z, v.w);
        *(__half2*)(dst + i) = h0;
        *(__half2*)(dst + i + 2) = h1;
    }
}

// ===========================================================================
// mma.sync fp16 GEMM (NT): C[m,n] = sum_k A[m,k]*B[n,k] (+bias), fp32 accum.
// cp.async double-buffered fp16 smem. CTA 128x128, BK=32, 8 warps 64x32.
// m16n8k16. Smem row stride 20 words (conflict-free fragment banks).
// qkv_mode=1 scatters C (fp32) into [B,H,T,HD].
// ===========================================================================
#define TBM 128
#define TBN 128
#define TBK 32
#define NKT (Dd / TBK)            // 64
#define HSTR 20                   // words per row: 16 data + 4 pad
#define TILE_HW (128 * HSTR)      // words per operand buffer
#define TCH_SMEM (4 * TILE_HW * 4)  // 2 buf x (A+B) = 40960 B

__global__ __launch_bounds__(256, 2) void tc_gemm_h(
    const __half* __restrict__ A, const __half* __restrict__ B,
    const float* __restrict__ bias, float* __restrict__ C, int qkv_mode)
{
    extern __shared__ uint32_t smw[];
    const uint32_t sbase = smem_u32(smw);

    const int tid = threadIdx.x;
    const int wid = tid >> 5;
    const int lane = tid & 31;
    const int grp = lane >> 2;
    const int tig = lane & 3;
    const int wm = (wid >> 2) * 64;
    const int wn = (wid & 3) * 32;
    const int row0 = blockIdx.y * TBM;
    const int col0 = blockIdx.x * TBN;

    // per-thread copy coords: 2 x 16B chunks (8 halfs) per operand per tile
    int lr[2], lwc[2], lhc[2];
    #pragma unroll
    for (int i = 0; i < 2; i++) {
        int c = tid + i * 256;       // 0..511
        lr[i] = c >> 2;              // row 0..127
        lwc[i] = (c & 3) * 4;        // word col 0,4,8,12
        lhc[i] = (c & 3) * 8;        // half col 0,8,16,24
    }

    float acc[4][4][4];
    #pragma unroll
    for (int mt = 0; mt < 4; mt++)
        #pragma unroll
        for (int nt = 0; nt < 4; nt++)
            #pragma unroll
            for (int e = 0; e < 4; e++) acc[mt][nt][e] = 0.f;

    // ---- prologue: async-copy tile 0 into buffer 0
    #pragma unroll
    for (int i = 0; i < 2; i++) {
        uint32_t so = (uint32_t)((lr[i] * HSTR + lwc[i]) * 4);
        cp16(sbase + so, A + (size_t)(row0 + lr[i]) * Dd + lhc[i]);
        cp16(sbase + TILE_HW * 4 + so, B + (size_t)(col0 + lr[i]) * Dd + lhc[i]);
    }
    asm volatile("cp.async.commit_group;");

    for (int kt = 0; kt < NKT; kt++) {
        const int b = kt & 1;
        const bool more = (kt + 1 < NKT);
        if (more) {
            const int k0 = (kt + 1) * TBK;
            const uint32_t abuf = sbase + (uint32_t)(b ^ 1) * 2u * TILE_HW * 4u;
            #pragma unroll
            for (int i = 0; i < 2; i++) {
                uint32_t so = (uint32_t)((lr[i] * HSTR + lwc[i]) * 4);
                cp16(abuf + so, A + (size_t)(row0 + lr[i]) * Dd + k0 + lhc[i]);
                cp16(abuf + TILE_HW * 4 + so, B + (size_t)(col0 + lr[i]) * Dd + k0 + lhc[i]);
            }
            asm volatile("cp.async.commit_group;");
            asm volatile("cp.async.wait_group 1;");
        } else {
            asm volatile("cp.async.wait_group 0;");
        }
        __syncthreads();

        const uint32_t* sA = smw + (size_t)b * 2 * TILE_HW;
        const uint32_t* sB = sA + TILE_HW;
        #pragma unroll
        for (int ks = 0; ks < 2; ks++) {       // two k16 steps per BK=32
            const int kk = ks * 8;             // word offset
            uint32_t af[4][4], bf[4][2];
            #pragma unroll
            for (int mt = 0; mt < 4; mt++) {
                const uint32_t* p = sA + (wm + mt * 16 + grp) * HSTR + kk + tig;
                af[mt][0] = p[0];
                af[mt][1] = p[8 * HSTR];
                af[mt][2] = p[4];
                af[mt][3] = p[8 * HSTR + 4];
            }
            #pragma unroll
            for (int nt = 0; nt < 4; nt++) {
                const uint32_t* p = sB + (wn + nt * 8 + grp) * HSTR + kk + tig;
                bf[nt][0] = p[0];
                bf[nt][1] = p[4];
            }
            #pragma unroll
            for (int mt = 0; mt < 4; mt++)
                #pragma unroll
                for (int nt = 0; nt < 4; nt++)
                    mma16816h(acc[mt][nt], af[mt], bf[nt], acc[mt][nt]);
        }
        __syncthreads();
    }

    // ---- epilogue (fp32 out)
    #pragma unroll
    for (int mt = 0; mt < 4; mt++) {
        const int mloc = wm + mt * 16 + grp;
        #pragma unroll
        for (int nt = 0; nt < 4; nt++) {
            const int cn = wn + nt * 8 + 2 * tig;
            float2 v0 = make_float2(acc[mt][nt][0], acc[mt][nt][1]);
            float2 v1 = make_float2(acc[mt][nt][2], acc[mt][nt][3]);
            if (qkv_mode) {
                const int h = col0 >> 7;
                #pragma unroll
                for (int rr = 0; rr < 2; rr++) {
                    int m = row0 + mloc + rr * 8;
                    int bb = m >> 11;
                    int t = m & (Tt - 1);
                    float* dst = C + ((size_t)(bb * Hh + h) * Tt + t) * HD + cn;
                    *(float2*)dst = rr ? v1 : v0;
                }
            } else {
                const int n = col0 + cn;
                if (bias) {
                    float2 bv = *(const float2*)(bias + n);
                    v0.x += bv.x; v0.y += bv.y;
                    v1.x += bv.x; v1.y += bv.y;
                }
                *(float2*)(C + (size_t)(row0 + mloc) * Dd + n) = v0;
                *(float2*)(C + (size_t)(row0 + mloc + 8) * Dd + n) = v1;
            }
        }
    }
}

// ===========================================================================
// Tensor-core causal flash attention (mma.sync tf32) [R7 proven]
// Only change: epilogue writes fp16 to g_ah (feeds O-projection).
// ===========================================================================
#define QS_STR 132
#define KS_STR 132
#define VS_STR 136
#define PS_STR 68
#define KS_OFF (128 * QS_STR)
#define VS_OFF (KS_OFF + 64 * KS_STR)
#define PS_OFF (VS_OFF + 64 * VS_STR)
#define ATN_SMEM ((PS_OFF + 128 * PS_STR) * 4)   // 171008 B

__global__ __launch_bounds__(256) void attn_tc(
    const float* __restrict__ Q, const float* __restrict__ K,
    const float* __restrict__ V, __half* __restrict__ Out)
{
    extern __shared__ uint32_t sw[];
    uint32_t* Qs = sw;             // [128][132]
    uint32_t* Ks = sw + KS_OFF;    // [64][132]
    uint32_t* Vs = sw + VS_OFF;    // [64][136]
    uint32_t* Ps = sw + PS_OFF;    // [128][68]

    const int tid = threadIdx.x;
    const int wid = tid >> 5;
    const int lane = tid & 31;
    const int grp = lane >> 2;     // 0..7
    const int tig = lane & 3;      // 0..3
    const int wm = wid * 16;       // warp row band
    const int qblk = (int)gridDim.x - 1 - (int)blockIdx.x;   // longest first
    const int bh = blockIdx.y;
    const float* Qp = Q + ((size_t)bh * Tt + qblk * 128) * HD;
    const float* Kp = K + (size_t)bh * Tt * HD;
    const float* Vp = V + (size_t)bh * Tt * HD;
    const float scale = 0.08838834764831845f;   // 1/sqrt(128)

    // Stage Q tile (128x128) -> Qs tf32
    #pragma unroll
    for (int i = 0; i < 16; i++) {
        int idx = tid + i * 256;
        int r = idx >> 5, c4 = idx & 31;
        float4 v = *(const float4*)(Qp + (size_t)r * HD + c4 * 4);
        *(uint4*)(Qs + r * QS_STR + c4 * 4) =
            make_uint4(f2tf32(v.x), f2tf32(v.y), f2tf32(v.z), f2tf32(v.w));
    }

    float o[16][4];
    #pragma unroll
    for (int nf = 0; nf < 16; nf++)
        #pragma unroll
        for (int e = 0; e < 4; e++) o[nf][e] = 0.f;
    float mi0 = -1e30f, mi1 = -1e30f, li0 = 0.f, li1 = 0.f;

    const int jmax = 2 * qblk + 1;
    const int r0g = qblk * 128 + wm + grp;
    const int r1g = r0g + 8;

    for (int jt = 0; jt <= jmax; jt++) {
        __syncthreads();
        #pragma unroll
        for (int i = 0; i < 8; i++) {
            int idx = tid + i * 256;
            int r = idx >> 5, c4 = idx & 31;
            float4 kv = *(const float4*)(Kp + (size_t)(jt * 64 + r) * HD + c4 * 4);
            *(uint4*)(Ks + r * KS_STR + c4 * 4) =
                make_uint4(f2tf32(kv.x), f2tf32(kv.y), f2tf32(kv.z), f2tf32(kv.w));
            float4 vv = *(const float4*)(Vp + (size_t)(jt * 64 + r) * HD + c4 * 4);
            *(uint4*)(Vs + r * VS_STR + c4 * 4) =
                make_uint4(f2tf32(vv.x), f2tf32(vv.y), f2tf32(vv.z), f2tf32(vv.w));
        }
        __syncthreads();

        // ---- S = Q K^T
        float s[8][4];
        #pragma unroll
        for (int nf = 0; nf < 8; nf++)
            #pragma unroll
            for (int e = 0; e < 4; e++) s[nf][e] = 0.f;

        #pragma unroll
        for (int ks = 0; ks < 16; ks++) {
            uint32_t a[4];
            const uint32_t* qp = Qs + (wm + grp) * QS_STR + ks * 8 + tig;
            a[0] = qp[0];
            a[1] = qp[8 * QS_STR];
            a[2] = qp[4];
            a[3] = qp[8 * QS_STR + 4];
            #pragma unroll
            for (int nf = 0; nf < 8; nf++) {
                uint32_t b[2];
                const uint32_t* kp = Ks + (nf * 8 + grp) * KS_STR + ks * 8 + tig;
                b[0] = kp[0];
                b[1] = kp[4];
                mma1688(s[nf], a, b, s[nf]);
            }
        }

        #pragma unroll
        for (int nf = 0; nf < 8; nf++)
            #pragma unroll
            for (int e = 0; e < 4; e++) s[nf][e] *= scale;
        if (jt >= 2 * qblk) {
            #pragma unroll
            for (int nf = 0; nf < 8; nf++) {
                int c0 = jt * 64 + nf * 8 + 2 * tig;
                if (c0     > r0g) s[nf][0] = -1e30f;
                if (c0 + 1 > r0g) s[nf][1] = -1e30f;
                if (c0     > r1g) s[nf][2] = -1e30f;
                if (c0 + 1 > r1g) s[nf][3] = -1e30f;
            }
        }

        // ---- warp-local online softmax
        float m0 = -1e30f, m1 = -1e30f;
        #pragma unroll
        for (int nf = 0; nf < 8; nf++) {
            m0 = fmaxf(m0, fmaxf(s[nf][0], s[nf][1]));
            m1 = fmaxf(m1, fmaxf(s[nf][2], s[nf][3]));
        }
        m0 = fmaxf(m0, __shfl_xor_sync(0xffffffffu, m0, 1));
        m0 = fmaxf(m0, __shfl_xor_sync(0xffffffffu, m0, 2));
        m1 = fmaxf(m1, __shfl_xor_sync(0xffffffffu, m1, 1));
        m1 = fmaxf(m1, __shfl_xor_sync(0xffffffffu, m1, 2));
        float mn0 = fmaxf(mi0, m0), mn1 = fmaxf(mi1, m1);
        float al0 = __expf(mi0 - mn0), al1 = __expf(mi1 - mn1);
        float sum0 = 0.f, sum1 = 0.f;
        #pragma unroll
        for (int nf = 0; nf < 8; nf++) {
            s[nf][0] = __expf(s[nf][0] - mn0);
            s[nf][1] = __expf(s[nf][1] - mn0);
            s[nf][2] = __expf(s[nf][2] - mn1);
            s[nf][3] = __expf(s[nf][3] - mn1);
            sum0 += s[nf][0] + s[nf][1];
            sum1 += s[nf][2] + s[nf][3];
        }
        sum0 += __shfl_xor_sync(0xffffffffu, sum0, 1);
        sum0 += __shfl_xor_sync(0xffffffffu, sum0, 2);
        sum1 += __shfl_xor_sync(0xffffffffu, sum1, 1);
        sum1 += __shfl_xor_sync(0xffffffffu, sum1, 2);
        li0 = li0 * al0 + sum0;  mi0 = mn0;
        li1 = li1 * al1 + sum1;  mi1 = mn1;
        #pragma unroll
        for (int nf = 0; nf < 16; nf++) {
            o[nf][0] *= al0; o[nf][1] *= al0;
            o[nf][2] *= al1; o[nf][3] *= al1;
        }

        // ---- stage P (tf32) to warp-private Ps rows
        #pragma unroll
        for (int nf = 0; nf < 8; nf++) {
            uint32_t* p0 = Ps + (wm + grp) * PS_STR + nf * 8 + 2 * tig;
            p0[0] = f2tf32(s[nf][0]); p0[1] = f2tf32(s[nf][1]);
            uint32_t* p1 = Ps + (wm + grp + 8) * PS_STR + nf * 8 + 2 * tig;
            p1[0] = f2tf32(s[nf][2]); p1[1] = f2tf32(s[nf][3]);
        }
        __syncwarp();

        // ---- O += P V
        #pragma unroll
        for (int ks = 0; ks < 8; ks++) {
            uint32_t a[4];
            const uint32_t* pp = Ps + (wm + grp) * PS_STR + ks * 8 + tig;
            a[0] = pp[0];
            a[1] = pp[8 * PS_STR];
            a[2] = pp[4];
            a[3] = pp[8 * PS_STR + 4];
            #pragma unroll
            for (int nf = 0; nf < 16; nf++) {
                uint32_t b[2];
                const uint32_t* vp = Vs + (ks * 8 + tig) * VS_STR + nf * 8 + grp;
                b[0] = vp[0];
                b[1] = vp[4 * VS_STR];
                mma1688(o[nf], a, b, o[nf]);
            }
        }
        __syncwarp();
    }

    // ---- epilogue: normalize, write fp16 to [B,T,D]
    const int b = bh >> 4, h = bh & 15;
    const int t0 = qblk * 128 + wm + grp;
    float inv0 = 1.0f / li0, inv1 = 1.0f / li1;
    __half* O0 = Out + ((size_t)(b * Tt + t0)) * Dd + h * HD;
    #pragma unroll
    for (int nf = 0; nf < 16; nf++) {
        int c = nf * 8 + 2 * tig;
        *(__half2*)(O0 + c) = __floats2half2_rn(o[nf][0] * inv0, o[nf][1] * inv0);
        *(__half2*)(O0 + (size_t)8 * Dd + c) = __floats2half2_rn(o[nf][2] * inv1, o[nf][3] * inv1);
    }
}

// ---------------------------------------------------------------------------
extern "C" void kernel_launch(void* const* d_in, const int* in_sizes, int n_in,
                              void* d_out, int out_size)
{
    const float* x  = (const float*)d_in[0];
    const float* Wq = (const float*)d_in[1];
    const float* Wk = (const float*)d_in[2];
    const float* Wv = (const float*)d_in[3];
    const float* Wo = (const float*)d_in[4];
    const float* bo = (const float*)d_in[5];

    float *q, *k, *v;
    __half *xh, *wh, *ah;
    cudaGetSymbolAddress((void**)&q, g_q);
    cudaGetSymbolAddress((void**)&k, g_k);
    cudaGetSymbolAddress((void**)&v, g_v);
    cudaGetSymbolAddress((void**)&xh, g_xh);
    cudaGetSymbolAddress((void**)&wh, g_wh);
    cudaGetSymbolAddress((void**)&ah, g_ah);

    cudaFuncSetAttribute(tc_gemm_h, cudaFuncAttributeMaxDynamicSharedMemorySize, TCH_SMEM);
    cudaFuncSetAttribute(attn_tc, cudaFuncAttributeMaxDynamicSharedMemorySize, ATN_SMEM);

    // fp32 -> fp16 pre-pass (x + 4 weights)
    cvt_fp16<<<dim3(512, 5), 256>>>(x, Wq, Wk, Wv, Wo);

    dim3 gg(Dd / TBN, Mrows / TBM);   // (16, 32)
    const size_t WN = (size_t)Dd * Dd;

    // QKV projections (fp16 mma + cp.async), scattered to [B,H,T,HD] fp32
    tc_gemm_h<<<gg, 256, TCH_SMEM>>>(xh, wh + 0 * WN, nullptr, q, 1);
    tc_gemm_h<<<gg, 256, TCH_SMEM>>>(xh, wh + 1 * WN, nullptr, k, 1);
    tc_gemm_h<<<gg, 256, TCH_SMEM>>>(xh, wh + 2 * WN, nullptr, v, 1);

    // Tensor-core causal attention -> g_ah (fp16)
    attn_tc<<<dim3(Tt / 128, Bz * Hh), 256, ATN_SMEM>>>(q, k, v, ah);

    // Output projection + bias (fp16 mma)
    tc_gemm_h<<<gg, 256, TCH_SMEM>>>(ah, wh + 3 * WN, bo, (float*)d_out, 0);
}

// round 11
// speedup vs baseline: 6.0756x; 1.1220x over previous
#include <cuda_runtime.h>
#include <cuda_fp16.h>
#include <cstdint>

#define Bz 2
#define Tt 2048
#define Dd 2048
#define Hh 16
#define HD 128
#define Mrows (Bz*Tt)

// Scratch (static device globals: allocation-free, graph-capture safe)
__device__ __half g_qh[Bz*Hh*Tt*HD];    // [B,H,T,HD] fp16
__device__ __half g_kh[Bz*Hh*Tt*HD];
__device__ __half g_vh[Bz*Hh*Tt*HD];
__device__ __half g_xh[Mrows*Dd];       // x in fp16
__device__ __half g_wh[4*Dd*Dd];        // Wq|Wk|Wv|Wo in fp16
__device__ __half g_ah[Mrows*Dd];       // attention output [B,T,D] fp16

__device__ __forceinline__ void mma16816h(float* d, const uint32_t* a,
                                          const uint32_t* b, const float* c) {
    asm volatile(
        "mma.sync.aligned.m16n8k16.row.col.f32.f16.f16.f32 "
        "{%0,%1,%2,%3}, {%4,%5,%6,%7}, {%8,%9}, {%10,%11,%12,%13};"
        : "=f"(d[0]), "=f"(d[1]), "=f"(d[2]), "=f"(d[3])
        : "r"(a[0]), "r"(a[1]), "r"(a[2]), "r"(a[3]),
          "r"(b[0]), "r"(b[1]),
          "f"(c[0]), "f"(c[1]), "f"(c[2]), "f"(c[3]));
}
__device__ __forceinline__ uint32_t smem_u32(const void* p) {
    uint32_t a;
    asm("{ .reg .u64 t; cvta.to.shared.u64 t, %1; cvt.u32.u64 %0, t; }" : "=r"(a) : "l"(p));
    return a;
}
__device__ __forceinline__ void cp16(uint32_t dst, const void* src) {
    asm volatile("cp.async.cg.shared.global [%0], [%1], 16;" :: "r"(dst), "l"(src));
}

// ===========================================================================
// fp32 -> fp16 conversion pre-pass (x + 4 weights)
// ===========================================================================
__global__ __launch_bounds__(256) void cvt_fp16(
    const float* __restrict__ x,
    const float* __restrict__ wq, const float* __restrict__ wk,
    const float* __restrict__ wv, const float* __restrict__ wo)
{
    const int sel = blockIdx.y;
    const float* src = (sel == 0) ? x : (sel == 1) ? wq : (sel == 2) ? wk
                       : (sel == 3) ? wv : wo;
    __half* dst = (sel == 0) ? g_xh : g_wh + (size_t)(sel - 1) * Dd * Dd;
    const int n = (sel == 0) ? Mrows * Dd : Dd * Dd;
    const int stride = gridDim.x * blockDim.x * 4;
    for (int i = (blockIdx.x * blockDim.x + threadIdx.x) * 4; i < n; i += stride) {
        float4 v = *(const float4*)(src + i);
        *(__half2*)(dst + i) = __floats2half2_rn(v.x, v.y);
        *(__half2*)(dst + i + 2) = __floats2half2_rn(v.z, v.w);
    }
}

// ===========================================================================
// mma.sync fp16 GEMM (NT): C = A B^T (+bias), fp32 accum. [R10 proven]
// qkv_mode=1: scatter fp16 into Ch [B,H,T,HD]; else fp32 into Cf (+bias).
// ===========================================================================
#define TBM 128
#define TBN 128
#define TBK 32
#define NKT (Dd / TBK)            // 64
#define HSTR 20                   // words per row: 16 data + 4 pad
#define TILE_HW (128 * HSTR)
#define TCH_SMEM (4 * TILE_HW * 4)  // 40960 B

__global__ __launch_bounds__(256, 2) void tc_gemm_h(
    const __half* __restrict__ A, const __half* __restrict__ B,
    const float* __restrict__ bias, float* __restrict__ Cf,
    __half* __restrict__ Ch, int qkv_mode)
{
    extern __shared__ uint32_t smw[];
    const uint32_t sbase = smem_u32(smw);

    const int tid = threadIdx.x;
    const int wid = tid >> 5;
    const int lane = tid & 31;
    const int grp = lane >> 2;
    const int tig = lane & 3;
    const int wm = (wid >> 2) * 64;
    const int wn = (wid & 3) * 32;
    const int row0 = blockIdx.y * TBM;
    const int col0 = blockIdx.x * TBN;

    int lr[2], lwc[2], lhc[2];
    #pragma unroll
    for (int i = 0; i < 2; i++) {
        int c = tid + i * 256;
        lr[i] = c >> 2;
        lwc[i] = (c & 3) * 4;
        lhc[i] = (c & 3) * 8;
    }

    float acc[4][4][4];
    #pragma unroll
    for (int mt = 0; mt < 4; mt++)
        #pragma unroll
        for (int nt = 0; nt < 4; nt++)
            #pragma unroll
            for (int e = 0; e < 4; e++) acc[mt][nt][e] = 0.f;

    #pragma unroll
    for (int i = 0; i < 2; i++) {
        uint32_t so = (uint32_t)((lr[i] * HSTR + lwc[i]) * 4);
        cp16(sbase + so, A + (size_t)(row0 + lr[i]) * Dd + lhc[i]);
        cp16(sbase + TILE_HW * 4 + so, B + (size_t)(col0 + lr[i]) * Dd + lhc[i]);
    }
    asm volatile("cp.async.commit_group;");

    for (int kt = 0; kt < NKT; kt++) {
        const int b = kt & 1;
        const bool more = (kt + 1 < NKT);
        if (more) {
            const int k0 = (kt + 1) * TBK;
            const uint32_t abuf = sbase + (uint32_t)(b ^ 1) * 2u * TILE_HW * 4u;
            #pragma unroll
            for (int i = 0; i < 2; i++) {
                uint32_t so = (uint32_t)((lr[i] * HSTR + lwc[i]) * 4);
                cp16(abuf + so, A + (size_t)(row0 + lr[i]) * Dd + k0 + lhc[i]);
                cp16(abuf + TILE_HW * 4 + so, B + (size_t)(col0 + lr[i]) * Dd + k0 + lhc[i]);
            }
            asm volatile("cp.async.commit_group;");
            asm volatile("cp.async.wait_group 1;");
        } else {
            asm volatile("cp.async.wait_group 0;");
        }
        __syncthreads();

        const uint32_t* sA = smw + (size_t)b * 2 * TILE_HW;
        const uint32_t* sB = sA + TILE_HW;
        #pragma unroll
        for (int ks = 0; ks < 2; ks++) {
            const int kk = ks * 8;
            uint32_t af[4][4], bf[4][2];
            #pragma unroll
            for (int mt = 0; mt < 4; mt++) {
                const uint32_t* p = sA + (wm + mt * 16 + grp) * HSTR + kk + tig;
                af[mt][0] = p[0];
                af[mt][1] = p[8 * HSTR];
                af[mt][2] = p[4];
                af[mt][3] = p[8 * HSTR + 4];
            }
            #pragma unroll
            for (int nt = 0; nt < 4; nt++) {
                const uint32_t* p = sB + (wn + nt * 8 + grp) * HSTR + kk + tig;
                bf[nt][0] = p[0];
                bf[nt][1] = p[4];
            }
            #pragma unroll
            for (int mt = 0; mt < 4; mt++)
                #pragma unroll
                for (int nt = 0; nt < 4; nt++)
                    mma16816h(acc[mt][nt], af[mt], bf[nt], acc[mt][nt]);
        }
        __syncthreads();
    }

    #pragma unroll
    for (int mt = 0; mt < 4; mt++) {
        const int mloc = wm + mt * 16 + grp;
        #pragma unroll
        for (int nt = 0; nt < 4; nt++) {
            const int cn = wn + nt * 8 + 2 * tig;
            float2 v0 = make_float2(acc[mt][nt][0], acc[mt][nt][1]);
            float2 v1 = make_float2(acc[mt][nt][2], acc[mt][nt][3]);
            if (qkv_mode) {
                const int h = col0 >> 7;
                #pragma unroll
                for (int rr = 0; rr < 2; rr++) {
                    int m = row0 + mloc + rr * 8;
                    int bb = m >> 11;
                    int t = m & (Tt - 1);
                    __half* dst = Ch + ((size_t)(bb * Hh + h) * Tt + t) * HD + cn;
                    float2 vv = rr ? v1 : v0;
                    *(__half2*)dst = __floats2half2_rn(vv.x, vv.y);
                }
            } else {
                const int n = col0 + cn;
                if (bias) {
                    float2 bv = *(const float2*)(bias + n);
                    v0.x += bv.x; v0.y += bv.y;
                    v1.x += bv.x; v1.y += bv.y;
                }
                *(float2*)(Cf + (size_t)(row0 + mloc) * Dd + n) = v0;
                *(float2*)(Cf + (size_t)(row0 + mloc + 8) * Dd + n) = v1;
            }
        }
    }
}

// ===========================================================================
// fp16 tensor-core causal flash attention (m16n8k16, fp32 accum)
// CTA: 128 q x 64-key tiles, 8 warps x 16-row bands, warp-local softmax.
// Smem 89KB -> 2 CTAs/SM.
// ===========================================================================
#define AQ_STR 68     // Q/K row stride in words (64 data + 4 pad)
#define AV_STR 36     // Vt / Ps row stride in words (32 data + 4 pad)
#define AKS_OFF (128 * AQ_STR)                 // 8704
#define AVT_OFF (AKS_OFF + 64 * AQ_STR)        // 13056
#define APS_OFF (AVT_OFF + 128 * AV_STR)       // 17664
#define ATNH_SMEM ((APS_OFF + 128 * AV_STR) * 4)   // 89088 B

__global__ __launch_bounds__(256, 2) void attn_h(
    const __half* __restrict__ Q, const __half* __restrict__ K,
    const __half* __restrict__ V, __half* __restrict__ Out)
{
    extern __shared__ uint32_t sw[];
    uint32_t* Qs = sw;               // [128][68]
    uint32_t* Ks = sw + AKS_OFF;     // [64][68]
    uint32_t* Vt = sw + AVT_OFF;     // [128 hd][36] (keys packed 2/word)
    uint32_t* Ps = sw + APS_OFF;     // [128][36]
    __half* svh = (__half*)sw;

    const int tid = threadIdx.x;
    const int wid = tid >> 5;
    const int lane = tid & 31;
    const int grp = lane >> 2;     // 0..7
    const int tig = lane & 3;      // 0..3
    const int wm = wid * 16;       // warp row band
    const int qblk = (int)gridDim.x - 1 - (int)blockIdx.x;   // longest first
    const int bh = blockIdx.y;
    const __half* Qp = Q + ((size_t)bh * Tt + qblk * 128) * HD;
    const __half* Kp = K + (size_t)bh * Tt * HD;
    const __half* Vp = V + (size_t)bh * Tt * HD;
    const float scale = 0.08838834764831845f;   // 1/sqrt(128)

    // Stage Q tile (128x128 halfs) once
    #pragma unroll
    for (int i = 0; i < 8; i++) {
        int idx = tid + i * 256;
        int r = idx >> 4, c8 = idx & 15;
        *(uint4*)(Qs + r * AQ_STR + c8 * 4) =
            *(const uint4*)(Qp + (size_t)r * HD + c8 * 8);
    }

    float o[16][4];
    #pragma unroll
    for (int nf = 0; nf < 16; nf++)
        #pragma unroll
        for (int e = 0; e < 4; e++) o[nf][e] = 0.f;
    float mi0 = -1e30f, mi1 = -1e30f, li0 = 0.f, li1 = 0.f;

    const int jmax = 2 * qblk + 1;
    const int r0g = qblk * 128 + wm + grp;
    const int r1g = r0g + 8;

    for (int jt = 0; jt <= jmax; jt++) {
        __syncthreads();   // prior tile reads done
        // Stage K tile (64x128 halfs) row-major
        #pragma unroll
        for (int i = 0; i < 4; i++) {
            int idx = tid + i * 256;
            int r = idx >> 4, c8 = idx & 15;
            *(uint4*)(Ks + r * AQ_STR + c8 * 4) =
                *(const uint4*)(Kp + (size_t)(jt * 64 + r) * HD + c8 * 8);
        }
        // Stage V tile transposed: Vt[hd][key]
        {
            const __half* VpT = Vp + (size_t)jt * 64 * HD;
            #pragma unroll
            for (int i = 0; i < 4; i++) {
                int idx = tid + i * 256;
                int r = idx & 63;        // key (lanes consecutive -> clean STS banks)
                int c8 = idx >> 6;       // hd block 0..15
                uint4 vv = *(const uint4*)(VpT + (size_t)r * HD + c8 * 8);
                const __half* hs = (const __half*)&vv;
                #pragma unroll
                for (int j = 0; j < 8; j++)
                    svh[(size_t)(AVT_OFF + (c8 * 8 + j) * AV_STR) * 2 + r] = hs[j];
            }
        }
        __syncthreads();

        // ---- S = Q K^T : warp computes [16 x 64], 8 k16-steps
        float s[8][4];
        #pragma unroll
        for (int nf = 0; nf < 8; nf++)
            #pragma unroll
            for (int e = 0; e < 4; e++) s[nf][e] = 0.f;

        #pragma unroll
        for (int ks = 0; ks < 8; ks++) {
            const int kk = ks * 8;
            uint32_t a[4];
            const uint32_t* qp = Qs + (wm + grp) * AQ_STR + kk + tig;
            a[0] = qp[0];
            a[1] = qp[8 * AQ_STR];
            a[2] = qp[4];
            a[3] = qp[8 * AQ_STR + 4];
            #pragma unroll
            for (int nf = 0; nf < 8; nf++) {
                uint32_t b[2];
                const uint32_t* kp = Ks + (nf * 8 + grp) * AQ_STR + kk + tig;
                b[0] = kp[0];
                b[1] = kp[4];
                mma16816h(s[nf], a, b, s[nf]);
            }
        }

        // scale + causal mask (diagonal key-blocks only)
        #pragma unroll
        for (int nf = 0; nf < 8; nf++)
            #pragma unroll
            for (int e = 0; e < 4; e++) s[nf][e] *= scale;
        if (jt >= 2 * qblk) {
            #pragma unroll
            for (int nf = 0; nf < 8; nf++) {
                int c0 = jt * 64 + nf * 8 + 2 * tig;
                if (c0     > r0g) s[nf][0] = -1e30f;
                if (c0 + 1 > r0g) s[nf][1] = -1e30f;
                if (c0     > r1g) s[nf][2] = -1e30f;
                if (c0 + 1 > r1g) s[nf][3] = -1e30f;
            }
        }

        // ---- warp-local online softmax (rows r0, r1)
        float m0 = -1e30f, m1 = -1e30f;
        #pragma unroll
        for (int nf = 0; nf < 8; nf++) {
            m0 = fmaxf(m0, fmaxf(s[nf][0], s[nf][1]));
            m1 = fmaxf(m1, fmaxf(s[nf][2], s[nf][3]));
        }
        m0 = fmaxf(m0, __shfl_xor_sync(0xffffffffu, m0, 1));
        m0 = fmaxf(m0, __shfl_xor_sync(0xffffffffu, m0, 2));
        m1 = fmaxf(m1, __shfl_xor_sync(0xffffffffu, m1, 1));
        m1 = fmaxf(m1, __shfl_xor_sync(0xffffffffu, m1, 2));
        float mn0 = fmaxf(mi0, m0), mn1 = fmaxf(mi1, m1);
        float al0 = __expf(mi0 - mn0), al1 = __expf(mi1 - mn1);
        float sum0 = 0.f, sum1 = 0.f;
        #pragma unroll
        for (int nf = 0; nf < 8; nf++) {
            s[nf][0] = __expf(s[nf][0] - mn0);
            s[nf][1] = __expf(s[nf][1] - mn0);
            s[nf][2] = __expf(s[nf][2] - mn1);
            s[nf][3] = __expf(s[nf][3] - mn1);
            sum0 += s[nf][0] + s[nf][1];
            sum1 += s[nf][2] + s[nf][3];
        }
        sum0 += __shfl_xor_sync(0xffffffffu, sum0, 1);
        sum0 += __shfl_xor_sync(0xffffffffu, sum0, 2);
        sum1 += __shfl_xor_sync(0xffffffffu, sum1, 1);
        sum1 += __shfl_xor_sync(0xffffffffu, sum1, 2);
        li0 = li0 * al0 + sum0;  mi0 = mn0;
        li1 = li1 * al1 + sum1;  mi1 = mn1;
        #pragma unroll
        for (int nf = 0; nf < 16; nf++) {
            o[nf][0] *= al0; o[nf][1] *= al0;
            o[nf][2] *= al1; o[nf][3] *= al1;
        }

        // ---- stage P (fp16 pairs) to warp-private Ps rows
        #pragma unroll
        for (int nf = 0; nf < 8; nf++) {
            ((__half2*)sw)[APS_OFF + (wm + grp) * AV_STR + nf * 4 + tig] =
                __floats2half2_rn(s[nf][0], s[nf][1]);
            ((__half2*)sw)[APS_OFF + (wm + grp + 8) * AV_STR + nf * 4 + tig] =
                __floats2half2_rn(s[nf][2], s[nf][3]);
        }
        __syncwarp();

        // ---- O += P V  (4 k16-steps over 64 keys, 16 hd n-tiles)
        #pragma unroll
        for (int ks = 0; ks < 4; ks++) {
            const int kk = ks * 8;
            uint32_t a[4];
            const uint32_t* pp = Ps + (wm + grp) * AV_STR + kk + tig;
            a[0] = pp[0];
            a[1] = pp[8 * AV_STR];
            a[2] = pp[4];
            a[3] = pp[8 * AV_STR + 4];
            #pragma unroll
            for (int nf = 0; nf < 16; nf++) {
                uint32_t b[2];
                const uint32_t* vp = Vt + (nf * 8 + grp) * AV_STR + kk + tig;
                b[0] = vp[0];
                b[1] = vp[4];
                mma16816h(o[nf], a, b, o[nf]);
            }
        }
        __syncwarp();   // Ps reads done before next jt overwrites
    }

    // ---- epilogue: normalize, write fp16 to [B,T,D]
    const int b = bh >> 4, h = bh & 15;
    const int t0 = qblk * 128 + wm + grp;
    float inv0 = 1.0f / li0, inv1 = 1.0f / li1;
    __half* O0 = Out + ((size_t)(b * Tt + t0)) * Dd + h * HD;
    #pragma unroll
    for (int nf = 0; nf < 16; nf++) {
        int c = nf * 8 + 2 * tig;
        *(__half2*)(O0 + c) = __floats2half2_rn(o[nf][0] * inv0, o[nf][1] * inv0);
        *(__half2*)(O0 + (size_t)8 * Dd + c) = __floats2half2_rn(o[nf][2] * inv1, o[nf][3] * inv1);
    }
}

// ---------------------------------------------------------------------------
extern "C" void kernel_launch(void* const* d_in, const int* in_sizes, int n_in,
                              void* d_out, int out_size)
{
    const float* x  = (const float*)d_in[0];
    const float* Wq = (const float*)d_in[1];
    const float* Wk = (const float*)d_in[2];
    const float* Wv = (const float*)d_in[3];
    const float* Wo = (const float*)d_in[4];
    const float* bo = (const float*)d_in[5];

    __half *qh, *kh, *vh, *xh, *wh, *ah;
    cudaGetSymbolAddress((void**)&qh, g_qh);
    cudaGetSymbolAddress((void**)&kh, g_kh);
    cudaGetSymbolAddress((void**)&vh, g_vh);
    cudaGetSymbolAddress((void**)&xh, g_xh);
    cudaGetSymbolAddress((void**)&wh, g_wh);
    cudaGetSymbolAddress((void**)&ah, g_ah);

    cudaFuncSetAttribute(tc_gemm_h, cudaFuncAttributeMaxDynamicSharedMemorySize, TCH_SMEM);
    cudaFuncSetAttribute(attn_h, cudaFuncAttributeMaxDynamicSharedMemorySize, ATNH_SMEM);

    // fp32 -> fp16 pre-pass (x + 4 weights)
    cvt_fp16<<<dim3(512, 5), 256>>>(x, Wq, Wk, Wv, Wo);

    dim3 gg(Dd / TBN, Mrows / TBM);   // (16, 32)
    const size_t WN = (size_t)Dd * Dd;

    // QKV projections (fp16 mma), scattered fp16 to [B,H,T,HD]
    tc_gemm_h<<<gg, 256, TCH_SMEM>>>(xh, wh + 0 * WN, nullptr, nullptr, qh, 1);
    tc_gemm_h<<<gg, 256, TCH_SMEM>>>(xh, wh + 1 * WN, nullptr, nullptr, kh, 1);
    tc_gemm_h<<<gg, 256, TCH_SMEM>>>(xh, wh + 2 * WN, nullptr, nullptr, vh, 1);

    // fp16 tensor-core causal attention -> g_ah (fp16)
    attn_h<<<dim3(Tt / 128, Bz * Hh), 256, ATNH_SMEM>>>(qh, kh, vh, ah);

    // Output projection + bias (fp16 mma, fp32 out)
    tc_gemm_h<<<gg, 256, TCH_SMEM>>>(ah, wh + 3 * WN, bo, (float*)d_out, nullptr, 0);
}

// round 12
// speedup vs baseline: 6.7281x; 1.1074x over previous
#include <cuda_runtime.h>
#include <cuda_fp16.h>
#include <cstdint>

#define Bz 2
#define Tt 2048
#define Dd 2048
#define Hh 16
#define HD 128
#define Mrows (Bz*Tt)
#define QKVS (Bz*Hh*Tt*HD)

// Scratch (static device globals: allocation-free, graph-capture safe)
__device__ __half g_qkvh[3*QKVS];       // Q|K|V [sel][B,H,T,HD] fp16
__device__ __half g_xh[Mrows*Dd];       // x in fp16
__device__ __half g_wh[4*Dd*Dd];        // Wq|Wk|Wv|Wo in fp16
__device__ __half g_ah[Mrows*Dd];       // attention output [B,T,D] fp16

__device__ __forceinline__ void mma16816h(float* d, const uint32_t* a,
                                          const uint32_t* b, const float* c) {
    asm volatile(
        "mma.sync.aligned.m16n8k16.row.col.f32.f16.f16.f32 "
        "{%0,%1,%2,%3}, {%4,%5,%6,%7}, {%8,%9}, {%10,%11,%12,%13};"
        : "=f"(d[0]), "=f"(d[1]), "=f"(d[2]), "=f"(d[3])
        : "r"(a[0]), "r"(a[1]), "r"(a[2]), "r"(a[3]),
          "r"(b[0]), "r"(b[1]),
          "f"(c[0]), "f"(c[1]), "f"(c[2]), "f"(c[3]));
}
__device__ __forceinline__ uint32_t smem_u32(const void* p) {
    uint32_t a;
    asm("{ .reg .u64 t; cvta.to.shared.u64 t, %1; cvt.u32.u64 %0, t; }" : "=r"(a) : "l"(p));
    return a;
}
__device__ __forceinline__ void cp16(uint32_t dst, const void* src) {
    asm volatile("cp.async.cg.shared.global [%0], [%1], 16;" :: "r"(dst), "l"(src));
}

// ===========================================================================
// fp32 -> fp16 conversion pre-pass (x + 4 weights)
// ===========================================================================
__global__ __launch_bounds__(256) void cvt_fp16(
    const float* __restrict__ x,
    const float* __restrict__ wq, const float* __restrict__ wk,
    const float* __restrict__ wv, const float* __restrict__ wo)
{
    const int sel = blockIdx.y;
    const float* src = (sel == 0) ? x : (sel == 1) ? wq : (sel == 2) ? wk
                       : (sel == 3) ? wv : wo;
    __half* dst = (sel == 0) ? g_xh : g_wh + (size_t)(sel - 1) * Dd * Dd;
    const int n = (sel == 0) ? Mrows * Dd : Dd * Dd;
    const int stride = gridDim.x * blockDim.x * 4;
    for (int i = (blockIdx.x * blockDim.x + threadIdx.x) * 4; i < n; i += stride) {
        float4 v = *(const float4*)(src + i);
        *(__half2*)(dst + i) = __floats2half2_rn(v.x, v.y);
        *(__half2*)(dst + i + 2) = __floats2half2_rn(v.z, v.w);
    }
}

// ===========================================================================
// mma.sync fp16 GEMM v3 (NT): C = A B^T (+bias), fp32 accum.
// 128 threads, 4 warps, warp tile 64x64 (2x reuse vs v2). CTA 128x128, BK=32.
// 3-stage cp.async pipeline, 1 syncthreads/kt. 2 CTAs/SM.
// qkv_mode=1: scatter fp16 into Ch[sel][B,H,T,HD] (sel = n-tile/16 heads).
// ===========================================================================
#define TBM 128
#define TBN 128
#define TBK 32
#define NKT (Dd / TBK)            // 64
#define HSTR 20                   // words per row: 16 data + 4 pad
#define TILE_HW (128 * HSTR)      // 2560 words per operand tile
#define NSTAGE 3
#define TCH_SMEM (NSTAGE * 2 * TILE_HW * 4)  // 61440 B

__global__ __launch_bounds__(128, 2) void tc_gemm_h(
    const __half* __restrict__ A, const __half* __restrict__ B,
    const float* __restrict__ bias, float* __restrict__ Cf,
    __half* __restrict__ Ch, int qkv_mode)
{
    extern __shared__ uint32_t smw[];
    const uint32_t sbase = smem_u32(smw);

    const int tid = threadIdx.x;
    const int wid = tid >> 5;
    const int lane = tid & 31;
    const int grp = lane >> 2;      // 0..7
    const int tig = lane & 3;       // 0..3
    const int wm = (wid >> 1) * 64; // 0/64
    const int wn = (wid & 1) * 64;  // 0/64
    const int row0 = blockIdx.y * TBM;
    const int col0 = blockIdx.x * TBN;

    // copy coords: per operand tile 512 x 16B chunks, 128 threads -> 4 each
    int lr[4], lwc[4], lhc[4];
    #pragma unroll
    for (int i = 0; i < 4; i++) {
        int c = tid + i * 128;       // 0..511
        lr[i] = c >> 2;              // row 0..127
        lwc[i] = (c & 3) * 4;        // word col
        lhc[i] = (c & 3) * 8;        // half col
    }

    float acc[4][8][4];
    #pragma unroll
    for (int mt = 0; mt < 4; mt++)
        #pragma unroll
        for (int nt = 0; nt < 8; nt++)
            #pragma unroll
            for (int e = 0; e < 4; e++) acc[mt][nt][e] = 0.f;

    // ---- prologue: stages 0,1
    #pragma unroll
    for (int s = 0; s < 2; s++) {
        const uint32_t buf = sbase + (uint32_t)s * 2u * TILE_HW * 4u;
        const int k0 = s * TBK;
        #pragma unroll
        for (int i = 0; i < 4; i++) {
            uint32_t so = (uint32_t)((lr[i] * HSTR + lwc[i]) * 4);
            cp16(buf + so, A + (size_t)(row0 + lr[i]) * Dd + k0 + lhc[i]);
            cp16(buf + TILE_HW * 4 + so, B + (size_t)(col0 + lr[i]) * Dd + k0 + lhc[i]);
        }
        asm volatile("cp.async.commit_group;");
    }

    int bc = 0, bl = 2;   // compute buffer, load buffer
    for (int kt = 0; kt < NKT; kt++) {
        if (kt < NKT - 1) asm volatile("cp.async.wait_group 1;");
        else              asm volatile("cp.async.wait_group 0;");
        __syncthreads();   // stage kt visible to all; prior compute of buf bl done

        if (kt + 2 < NKT) {
            const uint32_t buf = sbase + (uint32_t)bl * 2u * TILE_HW * 4u;
            const int k0 = (kt + 2) * TBK;
            #pragma unroll
            for (int i = 0; i < 4; i++) {
                uint32_t so = (uint32_t)((lr[i] * HSTR + lwc[i]) * 4);
                cp16(buf + so, A + (size_t)(row0 + lr[i]) * Dd + k0 + lhc[i]);
                cp16(buf + TILE_HW * 4 + so, B + (size_t)(col0 + lr[i]) * Dd + k0 + lhc[i]);
            }
            asm volatile("cp.async.commit_group;");
        }

        const uint32_t* sA = smw + (size_t)bc * 2 * TILE_HW;
        const uint32_t* sB = sA + TILE_HW;
        #pragma unroll
        for (int ks = 0; ks < 2; ks++) {
            const int kk = ks * 8;
            uint32_t af[4][4], bf[8][2];
            #pragma unroll
            for (int mt = 0; mt < 4; mt++) {
                const uint32_t* p = sA + (wm + mt * 16 + grp) * HSTR + kk + tig;
                af[mt][0] = p[0];
                af[mt][1] = p[8 * HSTR];
                af[mt][2] = p[4];
                af[mt][3] = p[8 * HSTR + 4];
            }
            #pragma unroll
            for (int nt = 0; nt < 8; nt++) {
                const uint32_t* p = sB + (wn + nt * 8 + grp) * HSTR + kk + tig;
                bf[nt][0] = p[0];
                bf[nt][1] = p[4];
            }
            #pragma unroll
            for (int mt = 0; mt < 4; mt++)
                #pragma unroll
                for (int nt = 0; nt < 8; nt++)
                    mma16816h(acc[mt][nt], af[mt], bf[nt], acc[mt][nt]);
        }
        bc = (bc + 1 == NSTAGE) ? 0 : bc + 1;
        bl = (bl + 1 == NSTAGE) ? 0 : bl + 1;
    }

    // ---- epilogue
    #pragma unroll
    for (int mt = 0; mt < 4; mt++) {
        const int mloc = wm + mt * 16 + grp;
        #pragma unroll
        for (int nt = 0; nt < 8; nt++) {
            const int cn = wn + nt * 8 + 2 * tig;
            float2 v0 = make_float2(acc[mt][nt][0], acc[mt][nt][1]);
            float2 v1 = make_float2(acc[mt][nt][2], acc[mt][nt][3]);
            if (qkv_mode) {
                const int hg = col0 >> 7;          // 0..47
                const int sel = hg >> 4;           // Q/K/V
                const int h = hg & 15;
                #pragma unroll
                for (int rr = 0; rr < 2; rr++) {
                    int m = row0 + mloc + rr * 8;
                    int bb = m >> 11;
                    int t = m & (Tt - 1);
                    __half* dst = Ch + (size_t)sel * QKVS +
                                  ((size_t)(bb * Hh + h) * Tt + t) * HD + cn;
                    float2 vv = rr ? v1 : v0;
                    *(__half2*)dst = __floats2half2_rn(vv.x, vv.y);
                }
            } else {
                const int n = col0 + cn;
                if (bias) {
                    float2 bv = *(const float2*)(bias + n);
                    v0.x += bv.x; v0.y += bv.y;
                    v1.x += bv.x; v1.y += bv.y;
                }
                *(float2*)(Cf + (size_t)(row0 + mloc) * Dd + n) = v0;
                *(float2*)(Cf + (size_t)(row0 + mloc + 8) * Dd + n) = v1;
            }
        }
    }
}

// ===========================================================================
// fp16 tensor-core causal flash attention (m16n8k16, fp32 accum) [R11 proven]
// ===========================================================================
#define AQ_STR 68
#define AV_STR 36
#define AKS_OFF (128 * AQ_STR)
#define AVT_OFF (AKS_OFF + 64 * AQ_STR)
#define APS_OFF (AVT_OFF + 128 * AV_STR)
#define ATNH_SMEM ((APS_OFF + 128 * AV_STR) * 4)   // 89088 B

__global__ __launch_bounds__(256, 2) void attn_h(
    const __half* __restrict__ Q, const __half* __restrict__ K,
    const __half* __restrict__ V, __half* __restrict__ Out)
{
    extern __shared__ uint32_t sw[];
    uint32_t* Qs = sw;               // [128][68]
    uint32_t* Ks = sw + AKS_OFF;     // [64][68]
    uint32_t* Vt = sw + AVT_OFF;     // [128 hd][36]
    uint32_t* Ps = sw + APS_OFF;     // [128][36]
    __half* svh = (__half*)sw;

    const int tid = threadIdx.x;
    const int wid = tid >> 5;
    const int lane = tid & 31;
    const int grp = lane >> 2;
    const int tig = lane & 3;
    const int wm = wid * 16;
    const int qblk = (int)gridDim.x - 1 - (int)blockIdx.x;
    const int bh = blockIdx.y;
    const __half* Qp = Q + ((size_t)bh * Tt + qblk * 128) * HD;
    const __half* Kp = K + (size_t)bh * Tt * HD;
    const __half* Vp = V + (size_t)bh * Tt * HD;
    const float scale = 0.08838834764831845f;

    #pragma unroll
    for (int i = 0; i < 8; i++) {
        int idx = tid + i * 256;
        int r = idx >> 4, c8 = idx & 15;
        *(uint4*)(Qs + r * AQ_STR + c8 * 4) =
            *(const uint4*)(Qp + (size_t)r * HD + c8 * 8);
    }

    float o[16][4];
    #pragma unroll
    for (int nf = 0; nf < 16; nf++)
        #pragma unroll
        for (int e = 0; e < 4; e++) o[nf][e] = 0.f;
    float mi0 = -1e30f, mi1 = -1e30f, li0 = 0.f, li1 = 0.f;

    const int jmax = 2 * qblk + 1;
    const int r0g = qblk * 128 + wm + grp;
    const int r1g = r0g + 8;

    for (int jt = 0; jt <= jmax; jt++) {
        __syncthreads();
        #pragma unroll
        for (int i = 0; i < 4; i++) {
            int idx = tid + i * 256;
            int r = idx >> 4, c8 = idx & 15;
            *(uint4*)(Ks + r * AQ_STR + c8 * 4) =
                *(const uint4*)(Kp + (size_t)(jt * 64 + r) * HD + c8 * 8);
        }
        {
            const __half* VpT = Vp + (size_t)jt * 64 * HD;
            #pragma unroll
            for (int i = 0; i < 4; i++) {
                int idx = tid + i * 256;
                int r = idx & 63;
                int c8 = idx >> 6;
                uint4 vv = *(const uint4*)(VpT + (size_t)r * HD + c8 * 8);
                const __half* hs = (const __half*)&vv;
                #pragma unroll
                for (int j = 0; j < 8; j++)
                    svh[(size_t)(AVT_OFF + (c8 * 8 + j) * AV_STR) * 2 + r] = hs[j];
            }
        }
        __syncthreads();

        float s[8][4];
        #pragma unroll
        for (int nf = 0; nf < 8; nf++)
            #pragma unroll
            for (int e = 0; e < 4; e++) s[nf][e] = 0.f;

        #pragma unroll
        for (int ks = 0; ks < 8; ks++) {
            const int kk = ks * 8;
            uint32_t a[4];
            const uint32_t* qp = Qs + (wm + grp) * AQ_STR + kk + tig;
            a[0] = qp[0];
            a[1] = qp[8 * AQ_STR];
            a[2] = qp[4];
            a[3] = qp[8 * AQ_STR + 4];
            #pragma unroll
            for (int nf = 0; nf < 8; nf++) {
                uint32_t b[2];
                const uint32_t* kp = Ks + (nf * 8 + grp) * AQ_STR + kk + tig;
                b[0] = kp[0];
                b[1] = kp[4];
                mma16816h(s[nf], a, b, s[nf]);
            }
        }

        #pragma unroll
        for (int nf = 0; nf < 8; nf++)
            #pragma unroll
            for (int e = 0; e < 4; e++) s[nf][e] *= scale;
        if (jt >= 2 * qblk) {
            #pragma unroll
            for (int nf = 0; nf < 8; nf++) {
                int c0 = jt * 64 + nf * 8 + 2 * tig;
                if (c0     > r0g) s[nf][0] = -1e30f;
                if (c0 + 1 > r0g) s[nf][1] = -1e30f;
                if (c0     > r1g) s[nf][2] = -1e30f;
                if (c0 + 1 > r1g) s[nf][3] = -1e30f;
            }
        }

        float m0 = -1e30f, m1 = -1e30f;
        #pragma unroll
        for (int nf = 0; nf < 8; nf++) {
            m0 = fmaxf(m0, fmaxf(s[nf][0], s[nf][1]));
            m1 = fmaxf(m1, fmaxf(s[nf][2], s[nf][3]));
        }
        m0 = fmaxf(m0, __shfl_xor_sync(0xffffffffu, m0, 1));
        m0 = fmaxf(m0, __shfl_xor_sync(0xffffffffu, m0, 2));
        m1 = fmaxf(m1, __shfl_xor_sync(0xffffffffu, m1, 1));
        m1 = fmaxf(m1, __shfl_xor_sync(0xffffffffu, m1, 2));
        float mn0 = fmaxf(mi0, m0), mn1 = fmaxf(mi1, m1);
        float al0 = __expf(mi0 - mn0), al1 = __expf(mi1 - mn1);
        float sum0 = 0.f, sum1 = 0.f;
        #pragma unroll
        for (int nf = 0; nf < 8; nf++) {
            s[nf][0] = __expf(s[nf][0] - mn0);
            s[nf][1] = __expf(s[nf][1] - mn0);
            s[nf][2] = __expf(s[nf][2] - mn1);
            s[nf][3] = __expf(s[nf][3] - mn1);
            sum0 += s[nf][0] + s[nf][1];
            sum1 += s[nf][2] + s[nf][3];
        }
        sum0 += __shfl_xor_sync(0xffffffffu, sum0, 1);
        sum0 += __shfl_xor_sync(0xffffffffu, sum0, 2);
        sum1 += __shfl_xor_sync(0xffffffffu, sum1, 1);
        sum1 += __shfl_xor_sync(0xffffffffu, sum1, 2);
        li0 = li0 * al0 + sum0;  mi0 = mn0;
        li1 = li1 * al1 + sum1;  mi1 = mn1;
        #pragma unroll
        for (int nf = 0; nf < 16; nf++) {
            o[nf][0] *= al0; o[nf][1] *= al0;
            o[nf][2] *= al1; o[nf][3] *= al1;
        }

        #pragma unroll
        for (int nf = 0; nf < 8; nf++) {
            ((__half2*)sw)[APS_OFF + (wm + grp) * AV_STR + nf * 4 + tig] =
                __floats2half2_rn(s[nf][0], s[nf][1]);
            ((__half2*)sw)[APS_OFF + (wm + grp + 8) * AV_STR + nf * 4 + tig] =
                __floats2half2_rn(s[nf][2], s[nf][3]);
        }
        __syncwarp();

        #pragma unroll
        for (int ks = 0; ks < 4; ks++) {
            const int kk = ks * 8;
            uint32_t a[4];
            const uint32_t* pp = Ps + (wm + grp) * AV_STR + kk + tig;
            a[0] = pp[0];
            a[1] = pp[8 * AV_STR];
            a[2] = pp[4];
            a[3] = pp[8 * AV_STR + 4];
            #pragma unroll
            for (int nf = 0; nf < 16; nf++) {
                uint32_t b[2];
                const uint32_t* vp = Vt + (nf * 8 + grp) * AV_STR + kk + tig;
                b[0] = vp[0];
                b[1] = vp[4];
                mma16816h(o[nf], a, b, o[nf]);
            }
        }
        __syncwarp();
    }

    const int b = bh >> 4, h = bh & 15;
    const int t0 = qblk * 128 + wm + grp;
    float inv0 = 1.0f / li0, inv1 = 1.0f / li1;
    __half* O0 = Out + ((size_t)(b * Tt + t0)) * Dd + h * HD;
    #pragma unroll
    for (int nf = 0; nf < 16; nf++) {
        int c = nf * 8 + 2 * tig;
        *(__half2*)(O0 + c) = __floats2half2_rn(o[nf][0] * inv0, o[nf][1] * inv0);
        *(__half2*)(O0 + (size_t)8 * Dd + c) = __floats2half2_rn(o[nf][2] * inv1, o[nf][3] * inv1);
    }
}

// ---------------------------------------------------------------------------
extern "C" void kernel_launch(void* const* d_in, const int* in_sizes, int n_in,
                              void* d_out, int out_size)
{
    const float* x  = (const float*)d_in[0];
    const float* Wq = (const float*)d_in[1];
    const float* Wk = (const float*)d_in[2];
    const float* Wv = (const float*)d_in[3];
    const float* Wv2 = (const float*)d_in[3];
    const float* Wo = (const float*)d_in[4];
    const float* bo = (const float*)d_in[5];
    (void)Wv2;

    __half *qkvh, *xh, *wh, *ah;
    cudaGetSymbolAddress((void**)&qkvh, g_qkvh);
    cudaGetSymbolAddress((void**)&xh, g_xh);
    cudaGetSymbolAddress((void**)&wh, g_wh);
    cudaGetSymbolAddress((void**)&ah, g_ah);

    cudaFuncSetAttribute(tc_gemm_h, cudaFuncAttributeMaxDynamicSharedMemorySize, TCH_SMEM);
    cudaFuncSetAttribute(attn_h, cudaFuncAttributeMaxDynamicSharedMemorySize, ATNH_SMEM);

    // fp32 -> fp16 pre-pass (x + 4 weights)
    cvt_fp16<<<dim3(512, 5), 256>>>(x, Wq, Wk, Wv, Wo);

    const size_t WN = (size_t)Dd * Dd;

    // Merged QKV projection: one GEMM over N = 3*Dd (Wq|Wk|Wv contiguous)
    tc_gemm_h<<<dim3(3 * Dd / TBN, Mrows / TBM), 128, TCH_SMEM>>>(
        xh, wh, nullptr, nullptr, qkvh, 1);

    // fp16 tensor-core causal attention -> g_ah (fp16)
    attn_h<<<dim3(Tt / 128, Bz * Hh), 256, ATNH_SMEM>>>(
        qkvh, qkvh + QKVS, qkvh + 2 * QKVS, ah);

    // Output projection + bias (fp16 mma, fp32 out)
    tc_gemm_h<<<dim3(Dd / TBN, Mrows / TBM), 128, TCH_SMEM>>>(
        ah, wh + 3 * WN, bo, (float*)d_out, nullptr, 0);
}

// round 13
// speedup vs baseline: 8.0087x; 1.1903x over previous
#include <cuda_runtime.h>
#include <cuda_fp16.h>
#include <cstdint>

#define Bz 2
#define Tt 2048
#define Dd 2048
#define Hh 16
#define HD 128
#define Mrows (Bz*Tt)
#define QKVS (Bz*Hh*Tt*HD)

// Scratch (static device globals: allocation-free, graph-capture safe)
__device__ __half g_qkvh[3*QKVS];       // Q|K|V [sel][B,H,T,HD] fp16
__device__ __half g_xh[Mrows*Dd];       // x in fp16
__device__ __half g_wh[4*Dd*Dd];        // Wq|Wk|Wv|Wo in fp16
__device__ __half g_ah[Mrows*Dd];       // attention output [B,T,D] fp16

__device__ __forceinline__ void mma16816h(float* d, const uint32_t* a,
                                          const uint32_t* b, const float* c) {
    asm volatile(
        "mma.sync.aligned.m16n8k16.row.col.f32.f16.f16.f32 "
        "{%0,%1,%2,%3}, {%4,%5,%6,%7}, {%8,%9}, {%10,%11,%12,%13};"
        : "=f"(d[0]), "=f"(d[1]), "=f"(d[2]), "=f"(d[3])
        : "r"(a[0]), "r"(a[1]), "r"(a[2]), "r"(a[3]),
          "r"(b[0]), "r"(b[1]),
          "f"(c[0]), "f"(c[1]), "f"(c[2]), "f"(c[3]));
}
__device__ __forceinline__ void ldsm4(uint32_t* r, uint32_t addr) {
    asm volatile("ldmatrix.sync.aligned.m8n8.x4.shared.b16 {%0,%1,%2,%3}, [%4];"
        : "=r"(r[0]), "=r"(r[1]), "=r"(r[2]), "=r"(r[3]) : "r"(addr));
}
__device__ __forceinline__ uint32_t smem_u32(const void* p) {
    uint32_t a;
    asm("{ .reg .u64 t; cvta.to.shared.u64 t, %1; cvt.u32.u64 %0, t; }" : "=r"(a) : "l"(p));
    return a;
}
__device__ __forceinline__ void cp16(uint32_t dst, const void* src) {
    asm volatile("cp.async.cg.shared.global [%0], [%1], 16;" :: "r"(dst), "l"(src));
}

// ===========================================================================
// fp32 -> fp16 conversion pre-pass (x + 4 weights)
// ===========================================================================
__global__ __launch_bounds__(256) void cvt_fp16(
    const float* __restrict__ x,
    const float* __restrict__ wq, const float* __restrict__ wk,
    const float* __restrict__ wv, const float* __restrict__ wo)
{
    const int sel = blockIdx.y;
    const float* src = (sel == 0) ? x : (sel == 1) ? wq : (sel == 2) ? wk
                       : (sel == 3) ? wv : wo;
    __half* dst = (sel == 0) ? g_xh : g_wh + (size_t)(sel - 1) * Dd * Dd;
    const int n = (sel == 0) ? Mrows * Dd : Dd * Dd;
    const int stride = gridDim.x * blockDim.x * 4;
    for (int i = (blockIdx.x * blockDim.x + threadIdx.x) * 4; i < n; i += stride) {
        float4 v = *(const float4*)(src + i);
        *(__half2*)(dst + i) = __floats2half2_rn(v.x, v.y);
        *(__half2*)(dst + i + 2) = __floats2half2_rn(v.z, v.w);
    }
}

// ===========================================================================
// mma.sync fp16 GEMM v4 (NT): C = A B^T (+bias), fp32 accum.
// 128 threads, 4 warps, warp tile 64x64. CTA 128x128, BK=32.
// 3-stage cp.async pipeline. Fragment loads via ldmatrix.x4 (16 LDSM/kt/warp).
// qkv_mode=1: scatter fp16 into Ch[sel][B,H,T,HD].
// ===========================================================================
#define TBM 128
#define TBN 128
#define TBK 32
#define NKT (Dd / TBK)            // 64
#define HSTR 20                   // words per row: 16 data + 4 pad
#define TILE_HW (128 * HSTR)      // 2560 words per operand tile
#define NSTAGE 3
#define TCH_SMEM (NSTAGE * 2 * TILE_HW * 4)  // 61440 B

__global__ __launch_bounds__(128, 2) void tc_gemm_h(
    const __half* __restrict__ A, const __half* __restrict__ B,
    const float* __restrict__ bias, float* __restrict__ Cf,
    __half* __restrict__ Ch, int qkv_mode)
{
    extern __shared__ uint32_t smw[];
    const uint32_t sbase = smem_u32(smw);

    const int tid = threadIdx.x;
    const int wid = tid >> 5;
    const int lane = tid & 31;
    const int grp = lane >> 2;
    const int tig = lane & 3;
    const int wm = (wid >> 1) * 64;
    const int wn = (wid & 1) * 64;
    const int row0 = blockIdx.y * TBM;
    const int col0 = blockIdx.x * TBN;

    // ldmatrix lane-address components
    const int rowA = wm + (lane & 15);              // + mt*16
    const int colA = ((lane >> 4) << 2);            // word offset 0/4
    const int rowB = wn + ((lane >> 4) << 3) + (lane & 7);   // + j*16
    const int colB = (((lane >> 3) & 1) << 2);      // word offset 0/4

    int lr[4], lwc[4], lhc[4];
    #pragma unroll
    for (int i = 0; i < 4; i++) {
        int c = tid + i * 128;
        lr[i] = c >> 2;
        lwc[i] = (c & 3) * 4;
        lhc[i] = (c & 3) * 8;
    }

    float acc[4][8][4];
    #pragma unroll
    for (int mt = 0; mt < 4; mt++)
        #pragma unroll
        for (int nt = 0; nt < 8; nt++)
            #pragma unroll
            for (int e = 0; e < 4; e++) acc[mt][nt][e] = 0.f;

    #pragma unroll
    for (int s = 0; s < 2; s++) {
        const uint32_t buf = sbase + (uint32_t)s * 2u * TILE_HW * 4u;
        const int k0 = s * TBK;
        #pragma unroll
        for (int i = 0; i < 4; i++) {
            uint32_t so = (uint32_t)((lr[i] * HSTR + lwc[i]) * 4);
            cp16(buf + so, A + (size_t)(row0 + lr[i]) * Dd + k0 + lhc[i]);
            cp16(buf + TILE_HW * 4 + so, B + (size_t)(col0 + lr[i]) * Dd + k0 + lhc[i]);
        }
        asm volatile("cp.async.commit_group;");
    }

    int bc = 0, bl = 2;
    for (int kt = 0; kt < NKT; kt++) {
        if (kt < NKT - 1) asm volatile("cp.async.wait_group 1;");
        else              asm volatile("cp.async.wait_group 0;");
        __syncthreads();

        if (kt + 2 < NKT) {
            const uint32_t buf = sbase + (uint32_t)bl * 2u * TILE_HW * 4u;
            const int k0 = (kt + 2) * TBK;
            #pragma unroll
            for (int i = 0; i < 4; i++) {
                uint32_t so = (uint32_t)((lr[i] * HSTR + lwc[i]) * 4);
                cp16(buf + so, A + (size_t)(row0 + lr[i]) * Dd + k0 + lhc[i]);
                cp16(buf + TILE_HW * 4 + so, B + (size_t)(col0 + lr[i]) * Dd + k0 + lhc[i]);
            }
            asm volatile("cp.async.commit_group;");
        }

        const uint32_t bufA = sbase + (uint32_t)bc * 2u * TILE_HW * 4u;
        const uint32_t bufB = bufA + TILE_HW * 4u;
        #pragma unroll
        for (int ks = 0; ks < 2; ks++) {
            const int kk = ks * 8;
            uint32_t af[4][4], bf[8][4];   // bf pairs: [2j],[2j]+2
            #pragma unroll
            for (int mt = 0; mt < 4; mt++)
                ldsm4(af[mt], bufA + (uint32_t)(((rowA + mt * 16) * HSTR + kk + colA) * 4));
            #pragma unroll
            for (int j = 0; j < 4; j++)
                ldsm4(bf[2 * j], bufB + (uint32_t)(((rowB + j * 16) * HSTR + kk + colB) * 4));
            #pragma unroll
            for (int mt = 0; mt < 4; mt++)
                #pragma unroll
                for (int j = 0; j < 4; j++) {
                    mma16816h(acc[mt][2 * j],     af[mt], &bf[2 * j][0], acc[mt][2 * j]);
                    mma16816h(acc[mt][2 * j + 1], af[mt], &bf[2 * j][2], acc[mt][2 * j + 1]);
                }
        }
        bc = (bc + 1 == NSTAGE) ? 0 : bc + 1;
        bl = (bl + 1 == NSTAGE) ? 0 : bl + 1;
    }

    #pragma unroll
    for (int mt = 0; mt < 4; mt++) {
        const int mloc = wm + mt * 16 + grp;
        #pragma unroll
        for (int nt = 0; nt < 8; nt++) {
            const int cn = wn + nt * 8 + 2 * tig;
            float2 v0 = make_float2(acc[mt][nt][0], acc[mt][nt][1]);
            float2 v1 = make_float2(acc[mt][nt][2], acc[mt][nt][3]);
            if (qkv_mode) {
                const int hg = col0 >> 7;
                const int sel = hg >> 4;
                const int h = hg & 15;
                #pragma unroll
                for (int rr = 0; rr < 2; rr++) {
                    int m = row0 + mloc + rr * 8;
                    int bb = m >> 11;
                    int t = m & (Tt - 1);
                    __half* dst = Ch + (size_t)sel * QKVS +
                                  ((size_t)(bb * Hh + h) * Tt + t) * HD + cn;
                    float2 vv = rr ? v1 : v0;
                    *(__half2*)dst = __floats2half2_rn(vv.x, vv.y);
                }
            } else {
                const int n = col0 + cn;
                if (bias) {
                    float2 bv = *(const float2*)(bias + n);
                    v0.x += bv.x; v0.y += bv.y;
                    v1.x += bv.x; v1.y += bv.y;
                }
                *(float2*)(Cf + (size_t)(row0 + mloc) * Dd + n) = v0;
                *(float2*)(Cf + (size_t)(row0 + mloc + 8) * Dd + n) = v1;
            }
        }
    }
}

// ===========================================================================
// fp16 tensor-core causal flash attention — fragments via ldmatrix.x4
// ===========================================================================
#define AQ_STR 68
#define AV_STR 36
#define AKS_OFF (128 * AQ_STR)
#define AVT_OFF (AKS_OFF + 64 * AQ_STR)
#define APS_OFF (AVT_OFF + 128 * AV_STR)
#define ATNH_SMEM ((APS_OFF + 128 * AV_STR) * 4)   // 89088 B

__global__ __launch_bounds__(256, 2) void attn_h(
    const __half* __restrict__ Q, const __half* __restrict__ K,
    const __half* __restrict__ V, __half* __restrict__ Out)
{
    extern __shared__ uint32_t sw[];
    const uint32_t abase = smem_u32(sw);
    __half* svh = (__half*)sw;

    const int tid = threadIdx.x;
    const int wid = tid >> 5;
    const int lane = tid & 31;
    const int grp = lane >> 2;
    const int tig = lane & 3;
    const int wm = wid * 16;
    const int qblk = (int)gridDim.x - 1 - (int)blockIdx.x;
    const int bh = blockIdx.y;
    const __half* Qp = Q + ((size_t)bh * Tt + qblk * 128) * HD;
    const __half* Kp = K + (size_t)bh * Tt * HD;
    const __half* Vp = V + (size_t)bh * Tt * HD;
    const float scale = 0.08838834764831845f;

    // ldmatrix lane-address components (A: 16-row frag; B: paired 8-row frags)
    const int rowA = lane & 15;
    const int colA = ((lane >> 4) << 2);
    const int rowB = ((lane >> 4) << 3) + (lane & 7);
    const int colB = (((lane >> 3) & 1) << 2);

    #pragma unroll
    for (int i = 0; i < 8; i++) {
        int idx = tid + i * 256;
        int r = idx >> 4, c8 = idx & 15;
        *(uint4*)(sw + r * AQ_STR + c8 * 4) =
            *(const uint4*)(Qp + (size_t)r * HD + c8 * 8);
    }

    float o[16][4];
    #pragma unroll
    for (int nf = 0; nf < 16; nf++)
        #pragma unroll
        for (int e = 0; e < 4; e++) o[nf][e] = 0.f;
    float mi0 = -1e30f, mi1 = -1e30f, li0 = 0.f, li1 = 0.f;

    const int jmax = 2 * qblk + 1;
    const int r0g = qblk * 128 + wm + grp;
    const int r1g = r0g + 8;

    for (int jt = 0; jt <= jmax; jt++) {
        __syncthreads();
        #pragma unroll
        for (int i = 0; i < 4; i++) {
            int idx = tid + i * 256;
            int r = idx >> 4, c8 = idx & 15;
            *(uint4*)(sw + AKS_OFF + r * AQ_STR + c8 * 4) =
                *(const uint4*)(Kp + (size_t)(jt * 64 + r) * HD + c8 * 8);
        }
        {
            const __half* VpT = Vp + (size_t)jt * 64 * HD;
            #pragma unroll
            for (int i = 0; i < 4; i++) {
                int idx = tid + i * 256;
                int r = idx & 63;
                int c8 = idx >> 6;
                uint4 vv = *(const uint4*)(VpT + (size_t)r * HD + c8 * 8);
                const __half* hs = (const __half*)&vv;
                #pragma unroll
                for (int j = 0; j < 8; j++)
                    svh[(size_t)(AVT_OFF + (c8 * 8 + j) * AV_STR) * 2 + r] = hs[j];
            }
        }
        __syncthreads();

        // ---- S = Q K^T  (8 k16-steps, fragments via LDSM)
        float s[8][4];
        #pragma unroll
        for (int nf = 0; nf < 8; nf++)
            #pragma unroll
            for (int e = 0; e < 4; e++) s[nf][e] = 0.f;

        #pragma unroll
        for (int ks = 0; ks < 8; ks++) {
            const int kk = ks * 8;
            uint32_t a[4];
            ldsm4(a, abase + (uint32_t)(((wm + rowA) * AQ_STR + kk + colA) * 4));
            #pragma unroll
            for (int j = 0; j < 4; j++) {
                uint32_t bp[4];
                ldsm4(bp, abase + (uint32_t)((AKS_OFF + (rowB + j * 16) * AQ_STR + kk + colB) * 4));
                mma16816h(s[2 * j],     a, &bp[0], s[2 * j]);
                mma16816h(s[2 * j + 1], a, &bp[2], s[2 * j + 1]);
            }
        }

        #pragma unroll
        for (int nf = 0; nf < 8; nf++)
            #pragma unroll
            for (int e = 0; e < 4; e++) s[nf][e] *= scale;
        if (jt >= 2 * qblk) {
            #pragma unroll
            for (int nf = 0; nf < 8; nf++) {
                int c0 = jt * 64 + nf * 8 + 2 * tig;
                if (c0     > r0g) s[nf][0] = -1e30f;
                if (c0 + 1 > r0g) s[nf][1] = -1e30f;
                if (c0     > r1g) s[nf][2] = -1e30f;
                if (c0 + 1 > r1g) s[nf][3] = -1e30f;
            }
        }

        float m0 = -1e30f, m1 = -1e30f;
        #pragma unroll
        for (int nf = 0; nf < 8; nf++) {
            m0 = fmaxf(m0, fmaxf(s[nf][0], s[nf][1]));
            m1 = fmaxf(m1, fmaxf(s[nf][2], s[nf][3]));
        }
        m0 = fmaxf(m0, __shfl_xor_sync(0xffffffffu, m0, 1));
        m0 = fmaxf(m0, __shfl_xor_sync(0xffffffffu, m0, 2));
        m1 = fmaxf(m1, __shfl_xor_sync(0xffffffffu, m1, 1));
        m1 = fmaxf(m1, __shfl_xor_sync(0xffffffffu, m1, 2));
        float mn0 = fmaxf(mi0, m0), mn1 = fmaxf(mi1, m1);
        float al0 = __expf(mi0 - mn0), al1 = __expf(mi1 - mn1);
        float sum0 = 0.f, sum1 = 0.f;
        #pragma unroll
        for (int nf = 0; nf < 8; nf++) {
            s[nf][0] = __expf(s[nf][0] - mn0);
            s[nf][1] = __expf(s[nf][1] - mn0);
            s[nf][2] = __expf(s[nf][2] - mn1);
            s[nf][3] = __expf(s[nf][3] - mn1);
            sum0 += s[nf][0] + s[nf][1];
            sum1 += s[nf][2] + s[nf][3];
        }
        sum0 += __shfl_xor_sync(0xffffffffu, sum0, 1);
        sum0 += __shfl_xor_sync(0xffffffffu, sum0, 2);
        sum1 += __shfl_xor_sync(0xffffffffu, sum1, 1);
        sum1 += __shfl_xor_sync(0xffffffffu, sum1, 2);
        li0 = li0 * al0 + sum0;  mi0 = mn0;
        li1 = li1 * al1 + sum1;  mi1 = mn1;
        #pragma unroll
        for (int nf = 0; nf < 16; nf++) {
            o[nf][0] *= al0; o[nf][1] *= al0;
            o[nf][2] *= al1; o[nf][3] *= al1;
        }

        #pragma unroll
        for (int nf = 0; nf < 8; nf++) {
            ((__half2*)sw)[APS_OFF + (wm + grp) * AV_STR + nf * 4 + tig] =
                __floats2half2_rn(s[nf][0], s[nf][1]);
            ((__half2*)sw)[APS_OFF + (wm + grp + 8) * AV_STR + nf * 4 + tig] =
                __floats2half2_rn(s[nf][2], s[nf][3]);
        }
        __syncwarp();

        // ---- O += P V  (4 k16-steps, fragments via LDSM)
        #pragma unroll
        for (int ks = 0; ks < 4; ks++) {
            const int kk = ks * 8;
            uint32_t a[4];
            ldsm4(a, abase + (uint32_t)((APS_OFF + (wm + rowA) * AV_STR + kk + colA) * 4));
            #pragma unroll
            for (int j = 0; j < 8; j++) {
                uint32_t bp[4];
                ldsm4(bp, abase + (uint32_t)((AVT_OFF + (rowB + j * 16) * AV_STR + kk + colB) * 4));
                mma16816h(o[2 * j],     a, &bp[0], o[2 * j]);
                mma16816h(o[2 * j + 1], a, &bp[2], o[2 * j + 1]);
            }
        }
        __syncwarp();
    }

    const int b = bh >> 4, h = bh & 15;
    const int t0 = qblk * 128 + wm + grp;
    float inv0 = 1.0f / li0, inv1 = 1.0f / li1;
    __half* O0 = Out + ((size_t)(b * Tt + t0)) * Dd + h * HD;
    #pragma unroll
    for (int nf = 0; nf < 16; nf++) {
        int c = nf * 8 + 2 * tig;
        *(__half2*)(O0 + c) = __floats2half2_rn(o[nf][0] * inv0, o[nf][1] * inv0);
        *(__half2*)(O0 + (size_t)8 * Dd + c) = __floats2half2_rn(o[nf][2] * inv1, o[nf][3] * inv1);
    }
}

// ---------------------------------------------------------------------------
extern "C" void kernel_launch(void* const* d_in, const int* in_sizes, int n_in,
                              void* d_out, int out_size)
{
    const float* x  = (const float*)d_in[0];
    const float* Wq = (const float*)d_in[1];
    const float* Wk = (const float*)d_in[2];
    const float* Wv = (const float*)d_in[3];
    const float* Wo = (const float*)d_in[4];
    const float* bo = (const float*)d_in[5];

    __half *qkvh, *xh, *wh, *ah;
    cudaGetSymbolAddress((void**)&qkvh, g_qkvh);
    cudaGetSymbolAddress((void**)&xh, g_xh);
    cudaGetSymbolAddress((void**)&wh, g_wh);
    cudaGetSymbolAddress((void**)&ah, g_ah);

    cudaFuncSetAttribute(tc_gemm_h, cudaFuncAttributeMaxDynamicSharedMemorySize, TCH_SMEM);
    cudaFuncSetAttribute(attn_h, cudaFuncAttributeMaxDynamicSharedMemorySize, ATNH_SMEM);

    // fp32 -> fp16 pre-pass (x + 4 weights)
    cvt_fp16<<<dim3(512, 5), 256>>>(x, Wq, Wk, Wv, Wo);

    const size_t WN = (size_t)Dd * Dd;

    // Merged QKV projection: one GEMM over N = 3*Dd (Wq|Wk|Wv contiguous)
    tc_gemm_h<<<dim3(3 * Dd / TBN, Mrows / TBM), 128, TCH_SMEM>>>(
        xh, wh, nullptr, nullptr, qkvh, 1);

    // fp16 tensor-core causal attention -> g_ah (fp16)
    attn_h<<<dim3(Tt / 128, Bz * Hh), 256, ATNH_SMEM>>>(
        qkvh, qkvh + QKVS, qkvh + 2 * QKVS, ah);

    // Output projection + bias (fp16 mma, fp32 out)
    tc_gemm_h<<<dim3(Dd / TBN, Mrows / TBM), 128, TCH_SMEM>>>(
        ah, wh + 3 * WN, bo, (float*)d_out, nullptr, 0);
}

// round 14
// speedup vs baseline: 8.7472x; 1.0922x over previous
#include <cuda_runtime.h>
#include <cuda_fp16.h>
#include <cstdint>

#define Bz 2
#define Tt 2048
#define Dd 2048
#define Hh 16
#define HD 128
#define Mrows (Bz*Tt)
#define QKVS (Bz*Hh*Tt*HD)

// Scratch (static device globals: allocation-free, graph-capture safe)
__device__ __half g_qkvh[3*QKVS];       // Q|K|V [sel][B,H,T,HD] fp16
__device__ __half g_xh[Mrows*Dd];       // x in fp16
__device__ __half g_wh[4*Dd*Dd];        // Wq|Wk|Wv|Wo in fp16
__device__ __half g_ah[Mrows*Dd];       // attention output [B,T,D] fp16

__device__ __forceinline__ void mma16816h(float* d, const uint32_t* a,
                                          const uint32_t* b, const float* c) {
    asm volatile(
        "mma.sync.aligned.m16n8k16.row.col.f32.f16.f16.f32 "
        "{%0,%1,%2,%3}, {%4,%5,%6,%7}, {%8,%9}, {%10,%11,%12,%13};"
        : "=f"(d[0]), "=f"(d[1]), "=f"(d[2]), "=f"(d[3])
        : "r"(a[0]), "r"(a[1]), "r"(a[2]), "r"(a[3]),
          "r"(b[0]), "r"(b[1]),
          "f"(c[0]), "f"(c[1]), "f"(c[2]), "f"(c[3]));
}
__device__ __forceinline__ void ldsm4(uint32_t* r, uint32_t addr) {
    asm volatile("ldmatrix.sync.aligned.m8n8.x4.shared.b16 {%0,%1,%2,%3}, [%4];"
        : "=r"(r[0]), "=r"(r[1]), "=r"(r[2]), "=r"(r[3]) : "r"(addr));
}
__device__ __forceinline__ void ldsm4t(uint32_t* r, uint32_t addr) {
    asm volatile("ldmatrix.sync.aligned.m8n8.x4.trans.shared.b16 {%0,%1,%2,%3}, [%4];"
        : "=r"(r[0]), "=r"(r[1]), "=r"(r[2]), "=r"(r[3]) : "r"(addr));
}
__device__ __forceinline__ uint32_t smem_u32(const void* p) {
    uint32_t a;
    asm("{ .reg .u64 t; cvta.to.shared.u64 t, %1; cvt.u32.u64 %0, t; }" : "=r"(a) : "l"(p));
    return a;
}
__device__ __forceinline__ void cp16(uint32_t dst, const void* src) {
    asm volatile("cp.async.cg.shared.global [%0], [%1], 16;" :: "r"(dst), "l"(src));
}

// ===========================================================================
// fp32 -> fp16 conversion pre-pass (x + 4 weights)
// ===========================================================================
__global__ __launch_bounds__(256) void cvt_fp16(
    const float* __restrict__ x,
    const float* __restrict__ wq, const float* __restrict__ wk,
    const float* __restrict__ wv, const float* __restrict__ wo)
{
    const int sel = blockIdx.y;
    const float* src = (sel == 0) ? x : (sel == 1) ? wq : (sel == 2) ? wk
                       : (sel == 3) ? wv : wo;
    __half* dst = (sel == 0) ? g_xh : g_wh + (size_t)(sel - 1) * Dd * Dd;
    const int n = (sel == 0) ? Mrows * Dd : Dd * Dd;
    const int stride = gridDim.x * blockDim.x * 4;
    for (int i = (blockIdx.x * blockDim.x + threadIdx.x) * 4; i < n; i += stride) {
        float4 v = *(const float4*)(src + i);
        *(__half2*)(dst + i) = __floats2half2_rn(v.x, v.y);
        *(__half2*)(dst + i + 2) = __floats2half2_rn(v.z, v.w);
    }
}

// ===========================================================================
// mma.sync fp16 GEMM v4 (NT)  [R13 proven — unchanged]
// ===========================================================================
#define TBM 128
#define TBN 128
#define TBK 32
#define NKT (Dd / TBK)            // 64
#define HSTR 20
#define TILE_HW (128 * HSTR)
#define NSTAGE 3
#define TCH_SMEM (NSTAGE * 2 * TILE_HW * 4)  // 61440 B

__global__ __launch_bounds__(128, 2) void tc_gemm_h(
    const __half* __restrict__ A, const __half* __restrict__ B,
    const float* __restrict__ bias, float* __restrict__ Cf,
    __half* __restrict__ Ch, int qkv_mode)
{
    extern __shared__ uint32_t smw[];
    const uint32_t sbase = smem_u32(smw);

    const int tid = threadIdx.x;
    const int wid = tid >> 5;
    const int lane = tid & 31;
    const int grp = lane >> 2;
    const int tig = lane & 3;
    const int wm = (wid >> 1) * 64;
    const int wn = (wid & 1) * 64;
    const int row0 = blockIdx.y * TBM;
    const int col0 = blockIdx.x * TBN;

    const int rowA = wm + (lane & 15);
    const int colA = ((lane >> 4) << 2);
    const int rowB = wn + ((lane >> 4) << 3) + (lane & 7);
    const int colB = (((lane >> 3) & 1) << 2);

    int lr[4], lwc[4], lhc[4];
    #pragma unroll
    for (int i = 0; i < 4; i++) {
        int c = tid + i * 128;
        lr[i] = c >> 2;
        lwc[i] = (c & 3) * 4;
        lhc[i] = (c & 3) * 8;
    }

    float acc[4][8][4];
    #pragma unroll
    for (int mt = 0; mt < 4; mt++)
        #pragma unroll
        for (int nt = 0; nt < 8; nt++)
            #pragma unroll
            for (int e = 0; e < 4; e++) acc[mt][nt][e] = 0.f;

    #pragma unroll
    for (int s = 0; s < 2; s++) {
        const uint32_t buf = sbase + (uint32_t)s * 2u * TILE_HW * 4u;
        const int k0 = s * TBK;
        #pragma unroll
        for (int i = 0; i < 4; i++) {
            uint32_t so = (uint32_t)((lr[i] * HSTR + lwc[i]) * 4);
            cp16(buf + so, A + (size_t)(row0 + lr[i]) * Dd + k0 + lhc[i]);
            cp16(buf + TILE_HW * 4 + so, B + (size_t)(col0 + lr[i]) * Dd + k0 + lhc[i]);
        }
        asm volatile("cp.async.commit_group;");
    }

    int bc = 0, bl = 2;
    for (int kt = 0; kt < NKT; kt++) {
        if (kt < NKT - 1) asm volatile("cp.async.wait_group 1;");
        else              asm volatile("cp.async.wait_group 0;");
        __syncthreads();

        if (kt + 2 < NKT) {
            const uint32_t buf = sbase + (uint32_t)bl * 2u * TILE_HW * 4u;
            const int k0 = (kt + 2) * TBK;
            #pragma unroll
            for (int i = 0; i < 4; i++) {
                uint32_t so = (uint32_t)((lr[i] * HSTR + lwc[i]) * 4);
                cp16(buf + so, A + (size_t)(row0 + lr[i]) * Dd + k0 + lhc[i]);
                cp16(buf + TILE_HW * 4 + so, B + (size_t)(col0 + lr[i]) * Dd + k0 + lhc[i]);
            }
            asm volatile("cp.async.commit_group;");
        }

        const uint32_t bufA = sbase + (uint32_t)bc * 2u * TILE_HW * 4u;
        const uint32_t bufB = bufA + TILE_HW * 4u;
        #pragma unroll
        for (int ks = 0; ks < 2; ks++) {
            const int kk = ks * 8;
            uint32_t af[4][4], bf[8][4];
            #pragma unroll
            for (int mt = 0; mt < 4; mt++)
                ldsm4(af[mt], bufA + (uint32_t)(((rowA + mt * 16) * HSTR + kk + colA) * 4));
            #pragma unroll
            for (int j = 0; j < 4; j++)
                ldsm4(bf[2 * j], bufB + (uint32_t)(((rowB + j * 16) * HSTR + kk + colB) * 4));
            #pragma unroll
            for (int mt = 0; mt < 4; mt++)
                #pragma unroll
                for (int j = 0; j < 4; j++) {
                    mma16816h(acc[mt][2 * j],     af[mt], &bf[2 * j][0], acc[mt][2 * j]);
                    mma16816h(acc[mt][2 * j + 1], af[mt], &bf[2 * j][2], acc[mt][2 * j + 1]);
                }
        }
        bc = (bc + 1 == NSTAGE) ? 0 : bc + 1;
        bl = (bl + 1 == NSTAGE) ? 0 : bl + 1;
    }

    #pragma unroll
    for (int mt = 0; mt < 4; mt++) {
        const int mloc = wm + mt * 16 + grp;
        #pragma unroll
        for (int nt = 0; nt < 8; nt++) {
            const int cn = wn + nt * 8 + 2 * tig;
            float2 v0 = make_float2(acc[mt][nt][0], acc[mt][nt][1]);
            float2 v1 = make_float2(acc[mt][nt][2], acc[mt][nt][3]);
            if (qkv_mode) {
                const int hg = col0 >> 7;
                const int sel = hg >> 4;
                const int h = hg & 15;
                #pragma unroll
                for (int rr = 0; rr < 2; rr++) {
                    int m = row0 + mloc + rr * 8;
                    int bb = m >> 11;
                    int t = m & (Tt - 1);
                    __half* dst = Ch + (size_t)sel * QKVS +
                                  ((size_t)(bb * Hh + h) * Tt + t) * HD + cn;
                    float2 vv = rr ? v1 : v0;
                    *(__half2*)dst = __floats2half2_rn(vv.x, vv.y);
                }
            } else {
                const int n = col0 + cn;
                if (bias) {
                    float2 bv = *(const float2*)(bias + n);
                    v0.x += bv.x; v0.y += bv.y;
                    v1.x += bv.x; v1.y += bv.y;
                }
                *(float2*)(Cf + (size_t)(row0 + mloc) * Dd + n) = v0;
                *(float2*)(Cf + (size_t)(row0 + mloc + 8) * Dd + n) = v1;
            }
        }
    }
}

// ===========================================================================
// fp16 tensor-core causal flash attention v2
// V row-major + ldmatrix.trans B-fragments (no scalar transpose staging);
// K/V staged via cp.async.
// ===========================================================================
#define AQ_STR 68     // Q/K/V row stride in words (64 data + 4 pad)
#define AV_STR 36     // Ps row stride in words
#define AKS_OFF (128 * AQ_STR)                 // 8704
#define AVS_OFF (AKS_OFF + 64 * AQ_STR)        // 13056
#define APS_OFF (AVS_OFF + 64 * AQ_STR)        // 17408
#define ATNH_SMEM ((APS_OFF + 128 * AV_STR) * 4)   // 88064 B

__global__ __launch_bounds__(256, 2) void attn_h(
    const __half* __restrict__ Q, const __half* __restrict__ K,
    const __half* __restrict__ V, __half* __restrict__ Out)
{
    extern __shared__ uint32_t sw[];
    const uint32_t abase = smem_u32(sw);

    const int tid = threadIdx.x;
    const int wid = tid >> 5;
    const int lane = tid & 31;
    const int grp = lane >> 2;
    const int tig = lane & 3;
    const int wm = wid * 16;
    const int qblk = (int)gridDim.x - 1 - (int)blockIdx.x;
    const int bh = blockIdx.y;
    const __half* Qp = Q + ((size_t)bh * Tt + qblk * 128) * HD;
    const __half* Kp = K + (size_t)bh * Tt * HD;
    const __half* Vp = V + (size_t)bh * Tt * HD;
    const float scale = 0.08838834764831845f;

    // ldmatrix lane-address components
    const int rowA = lane & 15;
    const int colA = ((lane >> 4) << 2);
    const int rowB = ((lane >> 4) << 3) + (lane & 7);
    const int colB = (((lane >> 3) & 1) << 2);
    const int krowT = lane & 15;            // trans-V: key-row within k16
    const int hdoT = ((lane >> 4) << 3);    // trans-V: hd offset 0/8

    // Stage Q tile once (128x128 halfs)
    #pragma unroll
    for (int i = 0; i < 8; i++) {
        int idx = tid + i * 256;
        int r = idx >> 4, c8 = idx & 15;
        *(uint4*)(sw + r * AQ_STR + c8 * 4) =
            *(const uint4*)(Qp + (size_t)r * HD + c8 * 8);
    }

    float o[16][4];
    #pragma unroll
    for (int nf = 0; nf < 16; nf++)
        #pragma unroll
        for (int e = 0; e < 4; e++) o[nf][e] = 0.f;
    float mi0 = -1e30f, mi1 = -1e30f, li0 = 0.f, li1 = 0.f;

    const int jmax = 2 * qblk + 1;
    const int r0g = qblk * 128 + wm + grp;
    const int r1g = r0g + 8;

    for (int jt = 0; jt <= jmax; jt++) {
        __syncthreads();   // prior K/V reads done before overwrite
        // Stage K + V tiles (64x128 halfs each) row-major via cp.async
        #pragma unroll
        for (int i = 0; i < 4; i++) {
            int idx = tid + i * 256;
            int r = idx >> 4, c8 = idx & 15;
            cp16(abase + (uint32_t)((AKS_OFF + r * AQ_STR + c8 * 4) * 4),
                 Kp + (size_t)(jt * 64 + r) * HD + c8 * 8);
            cp16(abase + (uint32_t)((AVS_OFF + r * AQ_STR + c8 * 4) * 4),
                 Vp + (size_t)(jt * 64 + r) * HD + c8 * 8);
        }
        asm volatile("cp.async.commit_group;");
        asm volatile("cp.async.wait_group 0;");
        __syncthreads();

        // ---- S = Q K^T  (8 k16-steps, fragments via LDSM)
        float s[8][4];
        #pragma unroll
        for (int nf = 0; nf < 8; nf++)
            #pragma unroll
            for (int e = 0; e < 4; e++) s[nf][e] = 0.f;

        #pragma unroll
        for (int ks = 0; ks < 8; ks++) {
            const int kk = ks * 8;
            uint32_t a[4];
            ldsm4(a, abase + (uint32_t)(((wm + rowA) * AQ_STR + kk + colA) * 4));
            #pragma unroll
            for (int j = 0; j < 4; j++) {
                uint32_t bp[4];
                ldsm4(bp, abase + (uint32_t)((AKS_OFF + (rowB + j * 16) * AQ_STR + kk + colB) * 4));
                mma16816h(s[2 * j],     a, &bp[0], s[2 * j]);
                mma16816h(s[2 * j + 1], a, &bp[2], s[2 * j + 1]);
            }
        }

        #pragma unroll
        for (int nf = 0; nf < 8; nf++)
            #pragma unroll
            for (int e = 0; e < 4; e++) s[nf][e] *= scale;
        if (jt >= 2 * qblk) {
            #pragma unroll
            for (int nf = 0; nf < 8; nf++) {
                int c0 = jt * 64 + nf * 8 + 2 * tig;
                if (c0     > r0g) s[nf][0] = -1e30f;
                if (c0 + 1 > r0g) s[nf][1] = -1e30f;
                if (c0     > r1g) s[nf][2] = -1e30f;
                if (c0 + 1 > r1g) s[nf][3] = -1e30f;
            }
        }

        // ---- warp-local online softmax
        float m0 = -1e30f, m1 = -1e30f;
        #pragma unroll
        for (int nf = 0; nf < 8; nf++) {
            m0 = fmaxf(m0, fmaxf(s[nf][0], s[nf][1]));
            m1 = fmaxf(m1, fmaxf(s[nf][2], s[nf][3]));
        }
        m0 = fmaxf(m0, __shfl_xor_sync(0xffffffffu, m0, 1));
        m0 = fmaxf(m0, __shfl_xor_sync(0xffffffffu, m0, 2));
        m1 = fmaxf(m1, __shfl_xor_sync(0xffffffffu, m1, 1));
        m1 = fmaxf(m1, __shfl_xor_sync(0xffffffffu, m1, 2));
        float mn0 = fmaxf(mi0, m0), mn1 = fmaxf(mi1, m1);
        float al0 = __expf(mi0 - mn0), al1 = __expf(mi1 - mn1);
        float sum0 = 0.f, sum1 = 0.f;
        #pragma unroll
        for (int nf = 0; nf < 8; nf++) {
            s[nf][0] = __expf(s[nf][0] - mn0);
            s[nf][1] = __expf(s[nf][1] - mn0);
            s[nf][2] = __expf(s[nf][2] - mn1);
            s[nf][3] = __expf(s[nf][3] - mn1);
            sum0 += s[nf][0] + s[nf][1];
            sum1 += s[nf][2] + s[nf][3];
        }
        sum0 += __shfl_xor_sync(0xffffffffu, sum0, 1);
        sum0 += __shfl_xor_sync(0xffffffffu, sum0, 2);
        sum1 += __shfl_xor_sync(0xffffffffu, sum1, 1);
        sum1 += __shfl_xor_sync(0xffffffffu, sum1, 2);
        li0 = li0 * al0 + sum0;  mi0 = mn0;
        li1 = li1 * al1 + sum1;  mi1 = mn1;
        #pragma unroll
        for (int nf = 0; nf < 16; nf++) {
            o[nf][0] *= al0; o[nf][1] *= al0;
            o[nf][2] *= al1; o[nf][3] *= al1;
        }

        // ---- stage P (fp16 pairs) to warp-private Ps rows
        #pragma unroll
        for (int nf = 0; nf < 8; nf++) {
            ((__half2*)sw)[APS_OFF + (wm + grp) * AV_STR + nf * 4 + tig] =
                __floats2half2_rn(s[nf][0], s[nf][1]);
            ((__half2*)sw)[APS_OFF + (wm + grp + 8) * AV_STR + nf * 4 + tig] =
                __floats2half2_rn(s[nf][2], s[nf][3]);
        }
        __syncwarp();

        // ---- O += P V  (V row-major, B-fragments via ldmatrix.trans)
        #pragma unroll
        for (int ks = 0; ks < 4; ks++) {
            uint32_t a[4];
            ldsm4(a, abase + (uint32_t)((APS_OFF + (wm + rowA) * AV_STR + ks * 8 + colA) * 4));
            const uint32_t vrow = abase +
                (uint32_t)((AVS_OFF + (ks * 16 + krowT) * AQ_STR) * 4);
            #pragma unroll
            for (int j = 0; j < 8; j++) {
                uint32_t bp[4];
                ldsm4t(bp, vrow + (uint32_t)((j * 16 + hdoT) * 2));
                mma16816h(o[2 * j],     a, &bp[0], o[2 * j]);
                mma16816h(o[2 * j + 1], a, &bp[2], o[2 * j + 1]);
            }
        }
        __syncwarp();   // Ps reads done before next jt overwrites
    }

    // ---- epilogue: normalize, write fp16 to [B,T,D]
    const int b = bh >> 4, h = bh & 15;
    const int t0 = qblk * 128 + wm + grp;
    float inv0 = 1.0f / li0, inv1 = 1.0f / li1;
    __half* O0 = Out + ((size_t)(b * Tt + t0)) * Dd + h * HD;
    #pragma unroll
    for (int nf = 0; nf < 16; nf++) {
        int c = nf * 8 + 2 * tig;
        *(__half2*)(O0 + c) = __floats2half2_rn(o[nf][0] * inv0, o[nf][1] * inv0);
        *(__half2*)(O0 + (size_t)8 * Dd + c) = __floats2half2_rn(o[nf][2] * inv1, o[nf][3] * inv1);
    }
}

// ---------------------------------------------------------------------------
extern "C" void kernel_launch(void* const* d_in, const int* in_sizes, int n_in,
                              void* d_out, int out_size)
{
    const float* x  = (const float*)d_in[0];
    const float* Wq = (const float*)d_in[1];
    const float* Wk = (const float*)d_in[2];
    const float* Wv = (const float*)d_in[3];
    const float* Wo = (const float*)d_in[4];
    const float* bo = (const float*)d_in[5];

    __half *qkvh, *xh, *wh, *ah;
    cudaGetSymbolAddress((void**)&qkvh, g_qkvh);
    cudaGetSymbolAddress((void**)&xh, g_xh);
    cudaGetSymbolAddress((void**)&wh, g_wh);
    cudaGetSymbolAddress((void**)&ah, g_ah);

    cudaFuncSetAttribute(tc_gemm_h, cudaFuncAttributeMaxDynamicSharedMemorySize, TCH_SMEM);
    cudaFuncSetAttribute(attn_h, cudaFuncAttributeMaxDynamicSharedMemorySize, ATNH_SMEM);

    // fp32 -> fp16 pre-pass (x + 4 weights)
    cvt_fp16<<<dim3(512, 5), 256>>>(x, Wq, Wk, Wv, Wo);

    const size_t WN = (size_t)Dd * Dd;

    // Merged QKV projection: one GEMM over N = 3*Dd (Wq|Wk|Wv contiguous)
    tc_gemm_h<<<dim3(3 * Dd / TBN, Mrows / TBM), 128, TCH_SMEM>>>(
        xh, wh, nullptr, nullptr, qkvh, 1);

    // fp16 tensor-core causal attention -> g_ah (fp16)
    attn_h<<<dim3(Tt / 128, Bz * Hh), 256, ATNH_SMEM>>>(
        qkvh, qkvh + QKVS, qkvh + 2 * QKVS, ah);

    // Output projection + bias (fp16 mma, fp32 out)
    tc_gemm_h<<<dim3(Dd / TBN, Mrows / TBM), 128, TCH_SMEM>>>(
        ah, wh + 3 * WN, bo, (float*)d_out, nullptr, 0);
}